// round 1
// baseline (speedup 1.0000x reference)
#include <cuda_runtime.h>

// LocalRNN: B=8, L=2048, D=256, KSIZE=8
// Plan:
//   Kernel 1: U = X @ Win + bias               (16384x256 @ 256x256)
//   Kernel 2: fused 8-step RNN. Each CTA holds a 64x256 H tile in SMEM,
//             streams W through SMEM, 7 GEMM steps + elementwise epilogue.
// Padded timesteps (t<0 within a batch) have x=0 -> u = bias.

namespace {
constexpr int Bb = 8;
constexpr int Ll = 2048;
constexpr int Dd = 256;
constexpr int Ks = 8;
constexpr int ROWS = Bb * Ll;   // 16384
constexpr int TM = 64;          // rows per CTA
constexpr int BK = 32;          // K-chunk
constexpr int NT = 256;         // threads per CTA
}

// Scratch for precomputed U = X @ Win + bias  (16 MB, device global = allowed)
__device__ float g_U[ROWS * Dd];

// ---------------------------------------------------------------------------
// Kernel 1: U = X @ Win + bias
// ---------------------------------------------------------------------------
__global__ __launch_bounds__(NT) void u_gemm_kernel(const float* __restrict__ X,
                                                    const float* __restrict__ Win,
                                                    const float* __restrict__ bias) {
    __shared__ float As[TM][BK];      // 8 KB
    __shared__ float Bs[BK][Dd];      // 32 KB
    const int r0 = blockIdx.x * TM;
    const int tid = threadIdx.x;
    const int tr = tid >> 5;          // 0..7
    const int tc = tid & 31;          // 0..31
    const int col0 = tc * 8;

    float acc[8][8];
#pragma unroll
    for (int i = 0; i < 8; i++)
#pragma unroll
        for (int j = 0; j < 8; j++) acc[i][j] = 0.f;

    for (int k0 = 0; k0 < Dd; k0 += BK) {
        __syncthreads();
        // Load A chunk (64x32): warp w loads rows {w, w+8, ...}, lanes = cols (coalesced)
#pragma unroll
        for (int i = 0; i < 8; i++) {
            int row = tr + 8 * i;
            As[row][tc] = X[(size_t)(r0 + row) * Dd + k0 + tc];
        }
        // Load B chunk (32x256) as float4 (coalesced)
#pragma unroll
        for (int i = 0; i < 8; i++) {
            int q = tid + NT * i;
            int kr = q >> 6;
            int c4 = (q & 63) * 4;
            *(float4*)&Bs[kr][c4] = *(const float4*)&Win[(size_t)(k0 + kr) * Dd + c4];
        }
        __syncthreads();
#pragma unroll
        for (int k = 0; k < BK; k++) {
            float a[8];
#pragma unroll
            for (int i = 0; i < 8; i++) a[i] = As[tr * 8 + i][k];
            float4 b0 = *(float4*)&Bs[k][col0];
            float4 b1 = *(float4*)&Bs[k][col0 + 4];
            float bb[8] = {b0.x, b0.y, b0.z, b0.w, b1.x, b1.y, b1.z, b1.w};
#pragma unroll
            for (int i = 0; i < 8; i++)
#pragma unroll
                for (int j = 0; j < 8; j++) acc[i][j] = fmaf(a[i], bb[j], acc[i][j]);
        }
    }

    float bj[8];
#pragma unroll
    for (int j = 0; j < 8; j++) bj[j] = bias[col0 + j];
#pragma unroll
    for (int i = 0; i < 8; i++) {
        const int r = r0 + tr * 8 + i;
        float4 o0, o1;
        o0.x = acc[i][0] + bj[0]; o0.y = acc[i][1] + bj[1];
        o0.z = acc[i][2] + bj[2]; o0.w = acc[i][3] + bj[3];
        o1.x = acc[i][4] + bj[4]; o1.y = acc[i][5] + bj[5];
        o1.z = acc[i][6] + bj[6]; o1.w = acc[i][7] + bj[7];
        *(float4*)&g_U[(size_t)r * Dd + col0]     = o0;
        *(float4*)&g_U[(size_t)r * Dd + col0 + 4] = o1;
    }
}

// ---------------------------------------------------------------------------
// Kernel 2: fused RNN.  H tile (64x256) lives in SMEM across all 8 steps.
//   step 0:  h = itau * relu(u_{l-7})                      (h0 = 0)
//   step k:  h = h + itau * (relu(H@W + u_{l-7+k}) - h)
// ---------------------------------------------------------------------------
__global__ __launch_bounds__(NT) void rnn_kernel(const float* __restrict__ W,
                                                 const float* __restrict__ bias,
                                                 const float* __restrict__ tau,
                                                 float* __restrict__ out) {
    extern __shared__ float smem[];
    float* Hs = smem;                 // TM * Dd  (64 KB)
    float* Ws = smem + TM * Dd;       // BK * Dd  (32 KB)

    const int r0 = blockIdx.x * TM;
    const int tid = threadIdx.x;
    const int tr = tid >> 5;
    const int tc = tid & 31;
    const int col0 = tc * 8;

    float itau[8], bj[8];
#pragma unroll
    for (int j = 0; j < 8; j++) {
        itau[j] = 1.f / tau[col0 + j];
        bj[j]   = bias[col0 + j];
    }

    // ---- step 0: h1 = itau * relu(u_{l-7}) ----
#pragma unroll
    for (int i = 0; i < 8; i++) {
        const int row = tr * 8 + i;
        const int r = r0 + row;
        const int l = r & (Ll - 1);
        float u[8];
        if (l - (Ks - 1) >= 0) {
            const float* up = g_U + (size_t)(r - (Ks - 1)) * Dd + col0;
            float4 u0 = *(const float4*)up;
            float4 u1 = *(const float4*)(up + 4);
            u[0] = u0.x; u[1] = u0.y; u[2] = u0.z; u[3] = u0.w;
            u[4] = u1.x; u[5] = u1.y; u[6] = u1.z; u[7] = u1.w;
        } else {
#pragma unroll
            for (int j = 0; j < 8; j++) u[j] = bj[j];
        }
#pragma unroll
        for (int j = 0; j < 8; j++)
            Hs[row * Dd + col0 + j] = itau[j] * fmaxf(u[j], 0.f);
    }

    // ---- steps 1..7: GEMM + pointwise update ----
    for (int step = 1; step < Ks; step++) {
        float acc[8][8];
#pragma unroll
        for (int i = 0; i < 8; i++)
#pragma unroll
            for (int j = 0; j < 8; j++) acc[i][j] = 0.f;

        for (int k0 = 0; k0 < Dd; k0 += BK) {
            __syncthreads();   // prior Hs writes / Ws reads complete
#pragma unroll
            for (int i = 0; i < 8; i++) {
                int q = tid + NT * i;
                int kr = q >> 6;
                int c4 = (q & 63) * 4;
                *(float4*)&Ws[kr * Dd + c4] =
                    *(const float4*)&W[(size_t)(k0 + kr) * Dd + c4];
            }
            __syncthreads();
#pragma unroll
            for (int k = 0; k < BK; k++) {
                float a[8];
#pragma unroll
                for (int i = 0; i < 8; i++) a[i] = Hs[(tr * 8 + i) * Dd + k0 + k];
                float4 b0 = *(float4*)&Ws[k * Dd + col0];
                float4 b1 = *(float4*)&Ws[k * Dd + col0 + 4];
                float bb[8] = {b0.x, b0.y, b0.z, b0.w, b1.x, b1.y, b1.z, b1.w};
#pragma unroll
                for (int i = 0; i < 8; i++)
#pragma unroll
                    for (int j = 0; j < 8; j++)
                        acc[i][j] = fmaf(a[i], bb[j], acc[i][j]);
            }
        }
        __syncthreads();   // everyone done reading Hs as the A operand

        const bool last = (step == Ks - 1);
#pragma unroll
        for (int i = 0; i < 8; i++) {
            const int row = tr * 8 + i;
            const int r = r0 + row;
            const int l = r & (Ll - 1);
            const int t = l - (Ks - 1) + step;
            float u[8];
            if (t >= 0) {
                const float* up = g_U + (size_t)(r - (Ks - 1) + step) * Dd + col0;
                float4 u0 = *(const float4*)up;
                float4 u1 = *(const float4*)(up + 4);
                u[0] = u0.x; u[1] = u0.y; u[2] = u0.z; u[3] = u0.w;
                u[4] = u1.x; u[5] = u1.y; u[6] = u1.z; u[7] = u1.w;
            } else {
#pragma unroll
                for (int j = 0; j < 8; j++) u[j] = bj[j];
            }
            if (last) {
                float4 o0, o1;
                float hn[8];
#pragma unroll
                for (int j = 0; j < 8; j++) {
                    float s = fmaxf(acc[i][j] + u[j], 0.f);
                    float h = Hs[row * Dd + col0 + j];
                    hn[j] = h + itau[j] * (s - h);
                }
                o0.x = hn[0]; o0.y = hn[1]; o0.z = hn[2]; o0.w = hn[3];
                o1.x = hn[4]; o1.y = hn[5]; o1.z = hn[6]; o1.w = hn[7];
                *(float4*)&out[(size_t)r * Dd + col0]     = o0;
                *(float4*)&out[(size_t)r * Dd + col0 + 4] = o1;
            } else {
#pragma unroll
                for (int j = 0; j < 8; j++) {
                    float s = fmaxf(acc[i][j] + u[j], 0.f);
                    float h = Hs[row * Dd + col0 + j];
                    Hs[row * Dd + col0 + j] = h + itau[j] * (s - h);
                }
            }
        }
    }
}

// ---------------------------------------------------------------------------
extern "C" void kernel_launch(void* const* d_in, const int* in_sizes, int n_in,
                              void* d_out, int out_size) {
    (void)in_sizes; (void)n_in; (void)out_size;
    const float* x            = (const float*)d_in[0];
    const float* weight       = (const float*)d_in[1];
    const float* input_weight = (const float*)d_in[2];
    const float* bias         = (const float*)d_in[3];
    const float* tau          = (const float*)d_in[4];
    float* out = (float*)d_out;

    u_gemm_kernel<<<ROWS / TM, NT>>>(x, input_weight, bias);

    const size_t smem_bytes = (size_t)(TM * Dd + BK * Dd) * sizeof(float);  // 96 KB
    cudaFuncSetAttribute(rnn_kernel, cudaFuncAttributeMaxDynamicSharedMemorySize,
                         (int)smem_bytes);
    rnn_kernel<<<ROWS / TM, NT, smem_bytes>>>(weight, bias, tau, out);
}

// round 3
// speedup vs baseline: 2.1967x; 2.1967x over previous
#include <cuda_runtime.h>
#include <cuda_bf16.h>
#include <cstdint>

// =====================================================================
// LocalRNN: B=8, L=2048, D=256, KSIZE=8   (sm_103 portable tensor path)
//  k0: w_prep — W^T split to bf16 hi/lo, chunk-major padded images
//  k1: u_gemm — U = X @ Win + bias (fp32 FFMA, known good)
//  k2: rnn    — fused 7-step recurrence on mma.sync.m16n8k16 (HMMA).
//      H in SMEM as bf16 hi/lo; 3-term split GEMM per step:
//        D = H_hi*W_hi + H_lo*W_hi + H_hi*W_lo
//      W streamed from L2 via cp.async.bulk 3-slot mbarrier ring.
// =====================================================================

namespace {
constexpr int Ll = 2048, Dd = 256, Ks = 8, ROWS = 16384;
// u_gemm
constexpr int UTM = 64, UBK = 32, UNT = 256;
// rnn
constexpr int TM   = 128;              // rows per CTA
constexpr int NT   = 256;              // 8 warps
constexpr int NCH  = 16;               // k-chunks of 16 per step
constexpr int RING = 3;
constexpr int WPITCH = 48;             // bytes per n-row in a chunk image
constexpr int CHB  = Dd * WPITCH;      // 12288 bytes (one chunk, one matrix)
constexpr int SLOT = 2 * CHB;          // hi + lo = 24576
constexpr int HSTR = 264;              // Hs row stride in bf16 (padded)
constexpr int HSB  = TM * HSTR * 2;    // 67584 bytes per Hs image
constexpr int SMEM_DYN = 2 * HSB + RING * SLOT;   // 208896
constexpr int GTOT = (Ks - 1) * NCH;   // 112 chunk-loads total
}

__device__ float g_U[ROWS * Dd];
__device__ __align__(16) __nv_bfloat16 g_Wt_hi[NCH * Dd * 24];
__device__ __align__(16) __nv_bfloat16 g_Wt_lo[NCH * Dd * 24];
__device__ float g_itau[Dd];

// ------------------------- PTX helpers --------------------------------
__device__ __forceinline__ uint32_t smem_u32(const void* p) {
    uint32_t a;
    asm("{ .reg .u64 t; cvta.to.shared.u64 t, %1; cvt.u32.u64 %0, t; }"
        : "=r"(a) : "l"(p));
    return a;
}

#define MBARRIER_INIT(mbar, cnt) \
    asm volatile("mbarrier.init.shared.b64 [%0], %1;" \
                 :: "r"((uint32_t)(mbar)), "r"((uint32_t)(cnt)) : "memory")
#define MBARRIER_ARRIVE(mbar) \
    asm volatile("mbarrier.arrive.shared.b64 _, [%0];" \
                 :: "r"((uint32_t)(mbar)) : "memory")
#define MBARRIER_EXPECT_TX(mbar, bytes) \
    asm volatile("mbarrier.arrive.expect_tx.shared.b64 _, [%0], %1;" \
                 :: "r"((uint32_t)(mbar)), "r"((uint32_t)(bytes)) : "memory")
#define MBARRIER_WAIT_PARITY(mbar, parity) do {                               \
    uint32_t _m = (uint32_t)(mbar);                                           \
    uint32_t _p = (uint32_t)(parity);                                         \
    uint32_t _done;                                                           \
    asm volatile(                                                             \
        "{\n\t.reg .pred p;\n\t"                                              \
        "mbarrier.try_wait.parity.acquire.cta.shared::cta.b64 p, [%1], %2;\n\t" \
        "selp.b32 %0, 1, 0, p;\n\t}"                                          \
        : "=r"(_done) : "r"(_m), "r"(_p) : "memory");                         \
    if (!_done) {                                                             \
        asm volatile(                                                         \
            "{\n\t.reg .pred P1;\n\t"                                         \
            "WL_%=:\n\t"                                                      \
            "mbarrier.try_wait.parity.acquire.cta.shared::cta.b64 P1, [%0], %1, 0x989680;\n\t" \
            "@P1 bra.uni WD_%=;\n\t"                                          \
            "bra.uni WL_%=;\n\t"                                              \
            "WD_%=:\n\t}"                                                     \
            :: "r"(_m), "r"(_p) : "memory");                                  \
    }                                                                         \
} while (0)

#define BULK_G2S(dst, src, bytes, mbar)                                       \
    asm volatile(                                                             \
        "cp.async.bulk.shared::cluster.global.mbarrier::complete_tx::bytes "  \
        "[%0], [%1], %2, [%3];"                                               \
        :: "r"((uint32_t)(dst)), "l"(src), "r"((uint32_t)(bytes)),            \
           "r"((uint32_t)(mbar)) : "memory")

#define LDSM_X4(r, addr)                                                      \
    asm volatile("ldmatrix.sync.aligned.m8n8.x4.shared.b16 "                  \
                 "{%0,%1,%2,%3}, [%4];"                                       \
                 : "=r"((r)[0]), "=r"((r)[1]), "=r"((r)[2]), "=r"((r)[3])     \
                 : "r"(addr))

#define MMA16816(d, a, b0_, b1_)                                              \
    asm volatile(                                                             \
        "mma.sync.aligned.m16n8k16.row.col.f32.bf16.bf16.f32 "                \
        "{%0,%1,%2,%3},{%4,%5,%6,%7},{%8,%9},{%0,%1,%2,%3};"                  \
        : "+f"((d)[0]), "+f"((d)[1]), "+f"((d)[2]), "+f"((d)[3])              \
        : "r"((a)[0]), "r"((a)[1]), "r"((a)[2]), "r"((a)[3]),                 \
          "r"(b0_), "r"(b1_))

__device__ __forceinline__ uint32_t pack_hi(float x, float y) {
    __nv_bfloat162 p;
    p.x = __float2bfloat16_rn(x);
    p.y = __float2bfloat16_rn(y);
    return *(uint32_t*)&p;
}
__device__ __forceinline__ uint32_t pack_lo(float x, float y, uint32_t hi) {
    __nv_bfloat162 h = *(__nv_bfloat162*)&hi;
    __nv_bfloat162 p;
    p.x = __float2bfloat16_rn(x - __bfloat162float(h.x));
    p.y = __float2bfloat16_rn(y - __bfloat162float(h.y));
    return *(uint32_t*)&p;
}

// ====================== k0: W prep ====================================
// Wt[chunk][n][k'] = W[k][n], k = chunk*16 + k', rows padded to 24 bf16.
__global__ void w_prep_kernel(const float* __restrict__ W,
                              const float* __restrict__ tau) {
    int idx = blockIdx.x * blockDim.x + threadIdx.x;  // 0..65535
    int k = idx >> 8, n = idx & 255;
    float w = W[k * Dd + n];
    __nv_bfloat16 hi = __float2bfloat16_rn(w);
    __nv_bfloat16 lo = __float2bfloat16_rn(w - __bfloat162float(hi));
    int off = ((k >> 4) * Dd + n) * 24 + (k & 15);
    g_Wt_hi[off] = hi;
    g_Wt_lo[off] = lo;
    if (idx < Dd) g_itau[idx] = 1.0f / tau[idx];
}

// ====================== k1: U = X @ Win + bias ========================
__global__ __launch_bounds__(UNT) void u_gemm_kernel(const float* __restrict__ X,
                                                     const float* __restrict__ Win,
                                                     const float* __restrict__ bias) {
    __shared__ float As[UTM][UBK];
    __shared__ float Bs[UBK][Dd];
    const int r0 = blockIdx.x * UTM;
    const int tid = threadIdx.x;
    const int tr = tid >> 5;
    const int tc = tid & 31;
    const int col0 = tc * 8;

    float acc[8][8];
#pragma unroll
    for (int i = 0; i < 8; i++)
#pragma unroll
        for (int j = 0; j < 8; j++) acc[i][j] = 0.f;

    for (int k0 = 0; k0 < Dd; k0 += UBK) {
        __syncthreads();
#pragma unroll
        for (int i = 0; i < 8; i++) {
            int row = tr + 8 * i;
            As[row][tc] = X[(size_t)(r0 + row) * Dd + k0 + tc];
        }
#pragma unroll
        for (int i = 0; i < 8; i++) {
            int q = tid + UNT * i;
            int kr = q >> 6;
            int c4 = (q & 63) * 4;
            *(float4*)&Bs[kr][c4] = *(const float4*)&Win[(size_t)(k0 + kr) * Dd + c4];
        }
        __syncthreads();
#pragma unroll
        for (int k = 0; k < UBK; k++) {
            float a[8];
#pragma unroll
            for (int i = 0; i < 8; i++) a[i] = As[tr * 8 + i][k];
            float4 b0 = *(float4*)&Bs[k][col0];
            float4 b1 = *(float4*)&Bs[k][col0 + 4];
            float bb[8] = {b0.x, b0.y, b0.z, b0.w, b1.x, b1.y, b1.z, b1.w};
#pragma unroll
            for (int i = 0; i < 8; i++)
#pragma unroll
                for (int j = 0; j < 8; j++) acc[i][j] = fmaf(a[i], bb[j], acc[i][j]);
        }
    }
    float bj[8];
#pragma unroll
    for (int j = 0; j < 8; j++) bj[j] = bias[col0 + j];
#pragma unroll
    for (int i = 0; i < 8; i++) {
        const int r = r0 + tr * 8 + i;
        float4 o0, o1;
        o0.x = acc[i][0] + bj[0]; o0.y = acc[i][1] + bj[1];
        o0.z = acc[i][2] + bj[2]; o0.w = acc[i][3] + bj[3];
        o1.x = acc[i][4] + bj[4]; o1.y = acc[i][5] + bj[5];
        o1.z = acc[i][6] + bj[6]; o1.w = acc[i][7] + bj[7];
        *(float4*)&g_U[(size_t)r * Dd + col0]     = o0;
        *(float4*)&g_U[(size_t)r * Dd + col0 + 4] = o1;
    }
}

// ====================== k2: fused HMMA RNN ============================
__global__ __launch_bounds__(NT, 1) void rnn_kernel(const float* __restrict__ bias,
                                                    float* __restrict__ out) {
    extern __shared__ __align__(128) char dsmem[];
    __shared__ __align__(8) uint64_t s_full[RING];
    __shared__ __align__(8) uint64_t s_empty[RING];

    const uint32_t hs_hi = smem_u32(dsmem);          // TM x HSTR bf16
    const uint32_t hs_lo = hs_hi + HSB;
    const uint32_t ring  = hs_lo + HSB;              // RING x SLOT
    const uint32_t mbf   = smem_u32(s_full);
    const uint32_t mbe   = smem_u32(s_empty);

    const int tid = threadIdx.x;
    const int wid = tid >> 5;
    const int t   = tid & 31;
    const int mi  = wid >> 2;   // 0/1 -> rows mi*64
    const int nj  = wid & 3;    // 0..3 -> cols nj*64

    if (tid == 0) {
        for (int i = 0; i < RING; i++) {
            MBARRIER_INIT(mbf + i * 8, 1);
            MBARRIER_INIT(mbe + i * 8, 8);
        }
    }
    __syncthreads();

    // Prime ring with chunks 0..2
    if (tid == 0) {
#pragma unroll
        for (int gg = 0; gg < RING; gg++) {
            uint32_t sb = ring + gg * SLOT;
            MBARRIER_EXPECT_TX(mbf + gg * 8, SLOT);
            BULK_G2S(sb,       (const char*)g_Wt_hi + gg * CHB, CHB, mbf + gg * 8);
            BULK_G2S(sb + CHB, (const char*)g_Wt_lo + gg * CHB, CHB, mbf + gg * 8);
        }
    }

    // ---- step 0: h1 = itau * relu(u_{l-7}) -> Hs hi/lo ----
    {
        const int row = tid >> 1;
        const int ch  = (tid & 1) * 128;
        const int gr  = blockIdx.x * TM + row;
        const int l   = gr & (Ll - 1);
        const float* us = (l >= Ks - 1)
            ? g_U + (size_t)(gr - (Ks - 1)) * Dd : bias;
#pragma unroll 8
        for (int cc = 0; cc < 128; cc += 2) {
            const int c = ch + cc;
            float2 u  = *(const float2*)(us + c);
            float2 it = *(const float2*)(g_itau + c);
            float h0 = it.x * fmaxf(u.x, 0.f);
            float h1 = it.y * fmaxf(u.y, 0.f);
            uint32_t hi = pack_hi(h0, h1);
            uint32_t lo = pack_lo(h0, h1, hi);
            *(uint32_t*)(dsmem + (size_t)(row * HSTR + c) * 2)       = hi;
            *(uint32_t*)(dsmem + HSB + (size_t)(row * HSTR + c) * 2) = lo;
        }
    }
    __syncthreads();

    // ldmatrix per-lane offsets
    const int a_r  = ((t >> 3) & 1) * 8 + (t & 7);  // row within m16 tile
    const int a_k  = ((t >> 4) & 1) * 8;            // k offset within chunk
    const int b_n  = ((t >> 4) & 1) * 8 + (t & 7);  // n within n16 group
    const int b_kb = ((t >> 3) & 1) * 16;           // k byte offset

    int g = 0;  // global chunk counter
    for (int step = 1; step < Ks; step++) {
        float D[4][8][4];
#pragma unroll
        for (int i = 0; i < 4; i++)
#pragma unroll
            for (int j = 0; j < 8; j++)
#pragma unroll
                for (int q = 0; q < 4; q++) D[i][j][q] = 0.f;

        for (int c = 0; c < NCH; c++, g++) {
            const uint32_t u3 = (uint32_t)g / 3u;
            const uint32_t s  = (uint32_t)g - u3 * 3u;
            const uint32_t ph = u3 & 1u;
            MBARRIER_WAIT_PARITY(mbf + s * 8, ph);

            // A fragments (hi/lo) for this k-chunk
            uint32_t AH[4][4], AL[4][4];
            const int kc = c * 16;
#pragma unroll
            for (int i = 0; i < 4; i++) {
                uint32_t off =
                    (uint32_t)((mi * 64 + i * 16 + a_r) * HSTR + kc + a_k) * 2;
                LDSM_X4(AH[i], hs_hi + off);
                LDSM_X4(AL[i], hs_lo + off);
            }

            const uint32_t sb = ring + s * SLOT;
            const uint32_t baddr = sb + (uint32_t)(nj * 64 + b_n) * 48 + b_kb;
#pragma unroll
            for (int jp = 0; jp < 4; jp++) {
                uint32_t BH[4], BL[4];
                LDSM_X4(BH, baddr + jp * 16 * 48);
                LDSM_X4(BL, baddr + jp * 16 * 48 + CHB);
#pragma unroll
                for (int i = 0; i < 4; i++) {
                    MMA16816(D[i][2 * jp],     AH[i], BH[0], BH[1]);
                    MMA16816(D[i][2 * jp],     AL[i], BH[0], BH[1]);
                    MMA16816(D[i][2 * jp],     AH[i], BL[0], BL[1]);
                    MMA16816(D[i][2 * jp + 1], AH[i], BH[2], BH[3]);
                    MMA16816(D[i][2 * jp + 1], AL[i], BH[2], BH[3]);
                    MMA16816(D[i][2 * jp + 1], AH[i], BL[2], BL[3]);
                }
            }
            __syncwarp();
            if (t == 0) MBARRIER_ARRIVE(mbe + s * 8);

            // producer: refill this slot with chunk g+3
            if (tid == 0) {
                const int gp = g + 3;
                if (gp < GTOT) {
                    MBARRIER_WAIT_PARITY(mbe + s * 8, ph);
                    const int cp = gp & 15;
                    MBARRIER_EXPECT_TX(mbf + s * 8, SLOT);
                    BULK_G2S(sb,       (const char*)g_Wt_hi + cp * CHB, CHB,
                             mbf + s * 8);
                    BULK_G2S(sb + CHB, (const char*)g_Wt_lo + cp * CHB, CHB,
                             mbf + s * 8);
                }
            }
        }
        __syncthreads();   // all A-reads of Hs done before epilogue writes

        // ---- fused epilogue: h' = h + itau*(relu(D+u) - h) ----
        const bool last = (step == Ks - 1);
#pragma unroll
        for (int i = 0; i < 4; i++) {
            const int rl0 = mi * 64 + i * 16 + (t >> 2);
#pragma unroll
            for (int half = 0; half < 2; half++) {
                const int rl = rl0 + half * 8;
                const int gr = blockIdx.x * TM + rl;
                const int tt = (gr & (Ll - 1)) - (Ks - 1) + step;
                const float* us = (tt >= 0)
                    ? g_U + (size_t)(gr - (Ks - 1) + step) * Dd : bias;
#pragma unroll
                for (int j = 0; j < 8; j++) {
                    const int cc = nj * 64 + j * 8 + 2 * (t & 3);
                    float2 u  = *(const float2*)(us + cc);
                    float2 it = *(const float2*)(g_itau + cc);
                    const float d0 = D[i][j][half * 2];
                    const float d1 = D[i][j][half * 2 + 1];
                    const size_t ho = (size_t)(rl * HSTR + cc) * 2;
                    uint32_t hv = *(uint32_t*)(dsmem + ho);
                    uint32_t lv = *(uint32_t*)(dsmem + HSB + ho);
                    __nv_bfloat162 hh = *(__nv_bfloat162*)&hv;
                    __nv_bfloat162 ll = *(__nv_bfloat162*)&lv;
                    float h0 = __bfloat162float(hh.x) + __bfloat162float(ll.x);
                    float h1 = __bfloat162float(hh.y) + __bfloat162float(ll.y);
                    float s0 = fmaxf(d0 + u.x, 0.f);
                    float s1 = fmaxf(d1 + u.y, 0.f);
                    float n0 = h0 + it.x * (s0 - h0);
                    float n1 = h1 + it.y * (s1 - h1);
                    if (last) {
                        *(float2*)(out + (size_t)gr * Dd + cc) =
                            make_float2(n0, n1);
                    } else {
                        uint32_t hi = pack_hi(n0, n1);
                        uint32_t lo = pack_lo(n0, n1, hi);
                        *(uint32_t*)(dsmem + ho)       = hi;
                        *(uint32_t*)(dsmem + HSB + ho) = lo;
                    }
                }
            }
        }
        if (!last) __syncthreads();   // Hs updated before next step's A-reads
    }
}

// ---------------------------------------------------------------------------
extern "C" void kernel_launch(void* const* d_in, const int* in_sizes, int n_in,
                              void* d_out, int out_size) {
    (void)in_sizes; (void)n_in; (void)out_size;
    const float* x            = (const float*)d_in[0];
    const float* weight       = (const float*)d_in[1];
    const float* input_weight = (const float*)d_in[2];
    const float* bias         = (const float*)d_in[3];
    const float* tau          = (const float*)d_in[4];
    float* out = (float*)d_out;

    w_prep_kernel<<<Dd * Dd / 256, 256>>>(weight, tau);
    u_gemm_kernel<<<ROWS / UTM, UNT>>>(x, input_weight, bias);

    cudaFuncSetAttribute(rnn_kernel, cudaFuncAttributeMaxDynamicSharedMemorySize,
                         SMEM_DYN);
    rnn_kernel<<<ROWS / TM, NT, SMEM_DYN>>>(bias, out);
}

// round 4
// speedup vs baseline: 3.4009x; 1.5482x over previous
#include <cuda_runtime.h>
#include <cuda_fp16.h>
#include <cstdint>

// =====================================================================
// LocalRNN: B=8, L=2048, D=256, KSIZE=8   (sm_103 portable HMMA path)
//  k0: w_prep — W -> fp16 single; Win -> fp16 hi/lo; chunk-major images
//  k1: u_gemm — U = X @ Win + bias on HMMA (X exact fp16 hi/lo split,
//               3-term => U error ~2^-22)
//  k2: rnn    — fused 7-step recurrence, 2-term fp16:
//               D = H_hi*W + H_lo*W   (H exact hi/lo, W fp16 => ~2^-12)
// =====================================================================

namespace {
constexpr int Ll = 2048, Dd = 256, Ks = 8, ROWS = 16384;
constexpr int TM   = 128;              // rows per CTA
constexpr int NT   = 256;              // 8 warps
constexpr int NCH  = 16;               // k-chunks of 16
constexpr int WPITCH = 48;             // bytes per n-row in a chunk image
constexpr int CHB  = Dd * WPITCH;      // 12288 bytes per chunk image
constexpr int HSTR = 264;              // H/X row stride in halfs (padded)
constexpr int HSB  = TM * HSTR * 2;    // 67584 bytes per image
// rnn: RING=6 slots of W (single image per chunk)
constexpr int RINGR = 6;
constexpr int SMEMR = 2 * HSB + RINGR * CHB;       // 208896
constexpr int GTOT  = (Ks - 1) * NCH;              // 112
// u_gemm: RING=3 slots of (Win_hi + Win_lo)
constexpr int RINGU = 3;
constexpr int USLOT = 2 * CHB;                     // 24576
constexpr int SMEMU = 2 * HSB + RINGU * USLOT;     // 208896
}

__device__ float g_U[ROWS * Dd];
__device__ __align__(16) __half g_Wf[NCH * Dd * 24];
__device__ __align__(16) __half g_WIhi[NCH * Dd * 24];
__device__ __align__(16) __half g_WIlo[NCH * Dd * 24];
__device__ float g_itau[Dd];

// ------------------------- PTX helpers --------------------------------
__device__ __forceinline__ uint32_t smem_u32(const void* p) {
    uint32_t a;
    asm("{ .reg .u64 t; cvta.to.shared.u64 t, %1; cvt.u32.u64 %0, t; }"
        : "=r"(a) : "l"(p));
    return a;
}

#define MBARRIER_INIT(mbar, cnt) \
    asm volatile("mbarrier.init.shared.b64 [%0], %1;" \
                 :: "r"((uint32_t)(mbar)), "r"((uint32_t)(cnt)) : "memory")
#define MBARRIER_ARRIVE(mbar) \
    asm volatile("mbarrier.arrive.shared.b64 _, [%0];" \
                 :: "r"((uint32_t)(mbar)) : "memory")
#define MBARRIER_EXPECT_TX(mbar, bytes) \
    asm volatile("mbarrier.arrive.expect_tx.shared.b64 _, [%0], %1;" \
                 :: "r"((uint32_t)(mbar)), "r"((uint32_t)(bytes)) : "memory")
#define MBARRIER_WAIT_PARITY(mbar, parity) do {                               \
    uint32_t _m = (uint32_t)(mbar);                                           \
    uint32_t _p = (uint32_t)(parity);                                         \
    uint32_t _done;                                                           \
    asm volatile(                                                             \
        "{\n\t.reg .pred p;\n\t"                                              \
        "mbarrier.try_wait.parity.acquire.cta.shared::cta.b64 p, [%1], %2;\n\t" \
        "selp.b32 %0, 1, 0, p;\n\t}"                                          \
        : "=r"(_done) : "r"(_m), "r"(_p) : "memory");                         \
    if (!_done) {                                                             \
        asm volatile(                                                         \
            "{\n\t.reg .pred P1;\n\t"                                         \
            "WL_%=:\n\t"                                                      \
            "mbarrier.try_wait.parity.acquire.cta.shared::cta.b64 P1, [%0], %1, 0x989680;\n\t" \
            "@P1 bra.uni WD_%=;\n\t"                                          \
            "bra.uni WL_%=;\n\t"                                              \
            "WD_%=:\n\t}"                                                     \
            :: "r"(_m), "r"(_p) : "memory");                                  \
    }                                                                         \
} while (0)

#define BULK_G2S(dst, src, bytes, mbar)                                       \
    asm volatile(                                                             \
        "cp.async.bulk.shared::cluster.global.mbarrier::complete_tx::bytes "  \
        "[%0], [%1], %2, [%3];"                                               \
        :: "r"((uint32_t)(dst)), "l"(src), "r"((uint32_t)(bytes)),            \
           "r"((uint32_t)(mbar)) : "memory")

#define LDSM_X4(r, addr)                                                      \
    asm volatile("ldmatrix.sync.aligned.m8n8.x4.shared.b16 "                  \
                 "{%0,%1,%2,%3}, [%4];"                                       \
                 : "=r"((r)[0]), "=r"((r)[1]), "=r"((r)[2]), "=r"((r)[3])     \
                 : "r"(addr))

#define MMAH(d, a, b0_, b1_)                                                  \
    asm volatile(                                                             \
        "mma.sync.aligned.m16n8k16.row.col.f32.f16.f16.f32 "                  \
        "{%0,%1,%2,%3},{%4,%5,%6,%7},{%8,%9},{%0,%1,%2,%3};"                  \
        : "+f"((d)[0]), "+f"((d)[1]), "+f"((d)[2]), "+f"((d)[3])              \
        : "r"((a)[0]), "r"((a)[1]), "r"((a)[2]), "r"((a)[3]),                 \
          "r"(b0_), "r"(b1_))

__device__ __forceinline__ uint32_t pack_hi(float x, float y) {
    __half2 p = __floats2half2_rn(x, y);
    return *(uint32_t*)&p;
}
__device__ __forceinline__ uint32_t pack_lo(float x, float y, uint32_t hi) {
    __half2 h = *(__half2*)&hi;
    __half2 p = __floats2half2_rn(x - __half2float(__low2half(h)),
                                  y - __half2float(__high2half(h)));
    return *(uint32_t*)&p;
}

// ====================== k0: W prep ====================================
// Images: [chunk][n][k'] with 24-half pitch; k = chunk*16 + k'.
__global__ void w_prep_kernel(const float* __restrict__ W,
                              const float* __restrict__ Win,
                              const float* __restrict__ tau) {
    int idx = blockIdx.x * blockDim.x + threadIdx.x;  // 0..65535
    int k = idx >> 8, n = idx & 255;
    int off = ((k >> 4) * Dd + n) * 24 + (k & 15);
    g_Wf[off] = __float2half_rn(W[k * Dd + n]);
    float wi = Win[k * Dd + n];
    __half hi = __float2half_rn(wi);
    g_WIhi[off] = hi;
    g_WIlo[off] = __float2half_rn(wi - __half2float(hi));
    if (idx < Dd) g_itau[idx] = 1.0f / tau[idx];
}

// ====================== k1: U = X @ Win + bias (HMMA) =================
__global__ __launch_bounds__(NT, 1) void u_gemm_kernel(const float* __restrict__ X,
                                                       const float* __restrict__ bias) {
    extern __shared__ __align__(128) char dsmem[];
    __shared__ __align__(8) uint64_t s_full[RINGU];
    __shared__ __align__(8) uint64_t s_empty[RINGU];

    const uint32_t xs_hi = smem_u32(dsmem);
    const uint32_t xs_lo = xs_hi + HSB;
    const uint32_t ring  = xs_lo + HSB;
    const uint32_t mbf   = smem_u32(s_full);
    const uint32_t mbe   = smem_u32(s_empty);

    const int tid = threadIdx.x;
    const int wid = tid >> 5;
    const int t   = tid & 31;
    const int mi  = wid >> 2;
    const int nj  = wid & 3;
    const int r0  = blockIdx.x * TM;

    if (tid == 0) {
        for (int i = 0; i < RINGU; i++) {
            MBARRIER_INIT(mbf + i * 8, 1);
            MBARRIER_INIT(mbe + i * 8, 8);
        }
    }
    __syncthreads();
    if (tid == 0) {
#pragma unroll
        for (int gg = 0; gg < RINGU; gg++) {
            uint32_t sb = ring + gg * USLOT;
            MBARRIER_EXPECT_TX(mbf + gg * 8, USLOT);
            BULK_G2S(sb,       (const char*)g_WIhi + gg * CHB, CHB, mbf + gg * 8);
            BULK_G2S(sb + CHB, (const char*)g_WIlo + gg * CHB, CHB, mbf + gg * 8);
        }
    }

    // ---- load X tile, split to fp16 hi/lo (coalesced: warp per row) ----
    for (int rr = wid; rr < TM; rr += 8) {
        const float* xr = X + (size_t)(r0 + rr) * Dd;
#pragma unroll
        for (int half = 0; half < 2; half++) {
            const int c = half * 128 + 4 * t;
            float4 v = *(const float4*)(xr + c);
            uint32_t h0 = pack_hi(v.x, v.y);
            uint32_t h1 = pack_hi(v.z, v.w);
            uint32_t l0 = pack_lo(v.x, v.y, h0);
            uint32_t l1 = pack_lo(v.z, v.w, h1);
            const size_t ho = (size_t)(rr * HSTR + c) * 2;
            *(uint32_t*)(dsmem + ho)           = h0;
            *(uint32_t*)(dsmem + ho + 4)       = h1;
            *(uint32_t*)(dsmem + HSB + ho)     = l0;
            *(uint32_t*)(dsmem + HSB + ho + 4) = l1;
        }
    }
    __syncthreads();

    const int a_r  = ((t >> 3) & 1) * 8 + (t & 7);
    const int a_k  = ((t >> 4) & 1) * 8;
    const int b_n  = ((t >> 4) & 1) * 8 + (t & 7);
    const int b_kb = ((t >> 3) & 1) * 16;

    float D[4][8][4];
#pragma unroll
    for (int i = 0; i < 4; i++)
#pragma unroll
        for (int j = 0; j < 8; j++)
#pragma unroll
            for (int q = 0; q < 4; q++) D[i][j][q] = 0.f;

    for (int g = 0; g < NCH; g++) {
        const int s  = g % RINGU;
        const uint32_t ph = ((uint32_t)g / RINGU) & 1u;
        MBARRIER_WAIT_PARITY(mbf + s * 8, ph);

        uint32_t AH[4][4], AL[4][4];
        const int kc = g * 16;
#pragma unroll
        for (int i = 0; i < 4; i++) {
            uint32_t off = (uint32_t)((mi * 64 + i * 16 + a_r) * HSTR + kc + a_k) * 2;
            LDSM_X4(AH[i], xs_hi + off);
            LDSM_X4(AL[i], xs_lo + off);
        }
        const uint32_t sb = ring + s * USLOT;
        const uint32_t baddr = sb + (uint32_t)(nj * 64 + b_n) * 48 + b_kb;
        uint32_t BH[4][4], BL[4][4];
#pragma unroll
        for (int jp = 0; jp < 4; jp++) {
            LDSM_X4(BH[jp], baddr + jp * 16 * 48);
            LDSM_X4(BL[jp], baddr + jp * 16 * 48 + CHB);
        }
        __syncwarp();
        if (t == 0) MBARRIER_ARRIVE(mbe + s * 8);

#pragma unroll
        for (int jp = 0; jp < 4; jp++)
#pragma unroll
            for (int i = 0; i < 4; i++) {
                MMAH(D[i][2 * jp],     AH[i], BH[jp][0], BH[jp][1]);
                MMAH(D[i][2 * jp],     AL[i], BH[jp][0], BH[jp][1]);
                MMAH(D[i][2 * jp],     AH[i], BL[jp][0], BL[jp][1]);
                MMAH(D[i][2 * jp + 1], AH[i], BH[jp][2], BH[jp][3]);
                MMAH(D[i][2 * jp + 1], AL[i], BH[jp][2], BH[jp][3]);
                MMAH(D[i][2 * jp + 1], AH[i], BL[jp][2], BL[jp][3]);
            }

        if (tid == 0 && g + RINGU < NCH) {
            MBARRIER_WAIT_PARITY(mbe + s * 8, ph);
            const int cp = g + RINGU;
            uint32_t sb2 = ring + s * USLOT;
            MBARRIER_EXPECT_TX(mbf + s * 8, USLOT);
            BULK_G2S(sb2,       (const char*)g_WIhi + cp * CHB, CHB, mbf + s * 8);
            BULK_G2S(sb2 + CHB, (const char*)g_WIlo + cp * CHB, CHB, mbf + s * 8);
        }
    }

    // ---- epilogue: U = D + bias ----
#pragma unroll
    for (int i = 0; i < 4; i++) {
#pragma unroll
        for (int half = 0; half < 2; half++) {
            const int rl = mi * 64 + i * 16 + (t >> 2) + half * 8;
            const int gr = r0 + rl;
#pragma unroll
            for (int j = 0; j < 8; j++) {
                const int cc = nj * 64 + j * 8 + 2 * (t & 3);
                float2 b = *(const float2*)(bias + cc);
                *(float2*)(g_U + (size_t)gr * Dd + cc) =
                    make_float2(D[i][j][half * 2] + b.x,
                                D[i][j][half * 2 + 1] + b.y);
            }
        }
    }
}

// ====================== k2: fused HMMA RNN (fp16 2-term) ==============
__global__ __launch_bounds__(NT, 1) void rnn_kernel(const float* __restrict__ bias,
                                                    float* __restrict__ out) {
    extern __shared__ __align__(128) char dsmem[];
    __shared__ __align__(8) uint64_t s_full[RINGR];
    __shared__ __align__(8) uint64_t s_empty[RINGR];

    const uint32_t hs_hi = smem_u32(dsmem);
    const uint32_t hs_lo = hs_hi + HSB;
    const uint32_t ring  = hs_lo + HSB;
    const uint32_t mbf   = smem_u32(s_full);
    const uint32_t mbe   = smem_u32(s_empty);

    const int tid = threadIdx.x;
    const int wid = tid >> 5;
    const int t   = tid & 31;
    const int mi  = wid >> 2;
    const int nj  = wid & 3;
    const int r0  = blockIdx.x * TM;

    if (tid == 0) {
        for (int i = 0; i < RINGR; i++) {
            MBARRIER_INIT(mbf + i * 8, 1);
            MBARRIER_INIT(mbe + i * 8, 8);
        }
    }
    __syncthreads();
    if (tid == 0) {
#pragma unroll
        for (int gg = 0; gg < RINGR; gg++) {
            MBARRIER_EXPECT_TX(mbf + gg * 8, CHB);
            BULK_G2S(ring + gg * CHB, (const char*)g_Wf + gg * CHB, CHB,
                     mbf + gg * 8);
        }
    }

    // ---- step 0: h1 = itau * relu(u_{l-7})  (coalesced warp-per-row) ----
    for (int rr = wid; rr < TM; rr += 8) {
        const int gr = r0 + rr;
        const int l  = gr & (Ll - 1);
        const float* us = (l >= Ks - 1) ? g_U + (size_t)(gr - (Ks - 1)) * Dd
                                        : bias;
#pragma unroll
        for (int half = 0; half < 2; half++) {
            const int c = half * 128 + 4 * t;
            float4 v  = *(const float4*)(us + c);
            float4 it = *(const float4*)(g_itau + c);
            float h0 = it.x * fmaxf(v.x, 0.f);
            float h1 = it.y * fmaxf(v.y, 0.f);
            float h2 = it.z * fmaxf(v.z, 0.f);
            float h3 = it.w * fmaxf(v.w, 0.f);
            uint32_t p0 = pack_hi(h0, h1);
            uint32_t p1 = pack_hi(h2, h3);
            uint32_t q0 = pack_lo(h0, h1, p0);
            uint32_t q1 = pack_lo(h2, h3, p1);
            const size_t ho = (size_t)(rr * HSTR + c) * 2;
            *(uint32_t*)(dsmem + ho)           = p0;
            *(uint32_t*)(dsmem + ho + 4)       = p1;
            *(uint32_t*)(dsmem + HSB + ho)     = q0;
            *(uint32_t*)(dsmem + HSB + ho + 4) = q1;
        }
    }
    __syncthreads();

    const int a_r  = ((t >> 3) & 1) * 8 + (t & 7);
    const int a_k  = ((t >> 4) & 1) * 8;
    const int b_n  = ((t >> 4) & 1) * 8 + (t & 7);
    const int b_kb = ((t >> 3) & 1) * 16;

    int g = 0;
    for (int step = 1; step < Ks; step++) {
        float D[4][8][4];
#pragma unroll
        for (int i = 0; i < 4; i++)
#pragma unroll
            for (int j = 0; j < 8; j++)
#pragma unroll
                for (int q = 0; q < 4; q++) D[i][j][q] = 0.f;

        for (int c = 0; c < NCH; c++, g++) {
            const uint32_t u6 = (uint32_t)g / RINGR;
            const uint32_t s  = (uint32_t)g - u6 * RINGR;
            const uint32_t ph = u6 & 1u;
            MBARRIER_WAIT_PARITY(mbf + s * 8, ph);

            uint32_t AH[4][4], AL[4][4];
            const int kc = c * 16;
#pragma unroll
            for (int i = 0; i < 4; i++) {
                uint32_t off =
                    (uint32_t)((mi * 64 + i * 16 + a_r) * HSTR + kc + a_k) * 2;
                LDSM_X4(AH[i], hs_hi + off);
                LDSM_X4(AL[i], hs_lo + off);
            }
            const uint32_t sb = ring + s * CHB;
            const uint32_t baddr = sb + (uint32_t)(nj * 64 + b_n) * 48 + b_kb;
            uint32_t BH[4][4];
#pragma unroll
            for (int jp = 0; jp < 4; jp++)
                LDSM_X4(BH[jp], baddr + jp * 16 * 48);
            __syncwarp();
            if (t == 0) MBARRIER_ARRIVE(mbe + s * 8);

#pragma unroll
            for (int jp = 0; jp < 4; jp++)
#pragma unroll
                for (int i = 0; i < 4; i++) {
                    MMAH(D[i][2 * jp],     AH[i], BH[jp][0], BH[jp][1]);
                    MMAH(D[i][2 * jp],     AL[i], BH[jp][0], BH[jp][1]);
                    MMAH(D[i][2 * jp + 1], AH[i], BH[jp][2], BH[jp][3]);
                    MMAH(D[i][2 * jp + 1], AL[i], BH[jp][2], BH[jp][3]);
                }

            // producer: refill this slot with chunk g+RINGR
            if (tid == 0 && g + RINGR < GTOT) {
                MBARRIER_WAIT_PARITY(mbe + s * 8, ph);
                const int cp = (g + RINGR) & 15;
                MBARRIER_EXPECT_TX(mbf + s * 8, CHB);
                BULK_G2S(ring + s * CHB, (const char*)g_Wf + cp * CHB, CHB,
                         mbf + s * 8);
            }
        }
        __syncthreads();   // all A-reads of Hs done before epilogue writes

        // ---- fused epilogue: h' = h + itau*(relu(D+u) - h) ----
        const bool last = (step == Ks - 1);
#pragma unroll
        for (int i = 0; i < 4; i++) {
            const int rl0 = mi * 64 + i * 16 + (t >> 2);
#pragma unroll
            for (int half = 0; half < 2; half++) {
                const int rl = rl0 + half * 8;
                const int gr = r0 + rl;
                const int tt = (gr & (Ll - 1)) - (Ks - 1) + step;
                const float* us = (tt >= 0)
                    ? g_U + (size_t)(gr - (Ks - 1) + step) * Dd : bias;
#pragma unroll
                for (int j = 0; j < 8; j++) {
                    const int cc = nj * 64 + j * 8 + 2 * (t & 3);
                    float2 u  = *(const float2*)(us + cc);
                    float2 it = *(const float2*)(g_itau + cc);
                    const float d0 = D[i][j][half * 2];
                    const float d1 = D[i][j][half * 2 + 1];
                    const size_t ho = (size_t)(rl * HSTR + cc) * 2;
                    uint32_t hv = *(uint32_t*)(dsmem + ho);
                    uint32_t lv = *(uint32_t*)(dsmem + HSB + ho);
                    __half2 hh = *(__half2*)&hv;
                    __half2 ll = *(__half2*)&lv;
                    float h0 = __half2float(__low2half(hh)) +
                               __half2float(__low2half(ll));
                    float h1 = __half2float(__high2half(hh)) +
                               __half2float(__high2half(ll));
                    float s0 = fmaxf(d0 + u.x, 0.f);
                    float s1 = fmaxf(d1 + u.y, 0.f);
                    float n0 = h0 + it.x * (s0 - h0);
                    float n1 = h1 + it.y * (s1 - h1);
                    if (last) {
                        *(float2*)(out + (size_t)gr * Dd + cc) =
                            make_float2(n0, n1);
                    } else {
                        uint32_t hi = pack_hi(n0, n1);
                        uint32_t lo = pack_lo(n0, n1, hi);
                        *(uint32_t*)(dsmem + ho)       = hi;
                        *(uint32_t*)(dsmem + HSB + ho) = lo;
                    }
                }
            }
        }
        if (!last) __syncthreads();
    }
}

// ---------------------------------------------------------------------------
extern "C" void kernel_launch(void* const* d_in, const int* in_sizes, int n_in,
                              void* d_out, int out_size) {
    (void)in_sizes; (void)n_in; (void)out_size;
    const float* x            = (const float*)d_in[0];
    const float* weight       = (const float*)d_in[1];
    const float* input_weight = (const float*)d_in[2];
    const float* bias         = (const float*)d_in[3];
    const float* tau          = (const float*)d_in[4];
    float* out = (float*)d_out;

    w_prep_kernel<<<Dd * Dd / 256, 256>>>(weight, input_weight, tau);

    cudaFuncSetAttribute(u_gemm_kernel, cudaFuncAttributeMaxDynamicSharedMemorySize,
                         SMEMU);
    u_gemm_kernel<<<ROWS / TM, NT, SMEMU>>>(x, bias);

    cudaFuncSetAttribute(rnn_kernel, cudaFuncAttributeMaxDynamicSharedMemorySize,
                         SMEMR);
    rnn_kernel<<<ROWS / TM, NT, SMEMR>>>(bias, out);
}

// round 5
// speedup vs baseline: 3.4927x; 1.0270x over previous
#include <cuda_runtime.h>
#include <cuda_fp16.h>
#include <cstdint>

// =====================================================================
// LocalRNN: B=8, L=2048, D=256, KSIZE=8   (sm_103 portable HMMA path)
// R5: each CTA = two independent 64-row groups (warps 0-3 / 4-7) with
//     private W rings + named barriers -> tensor pipe stays fed through
//     epilogue/sync bubbles. W chunk images packed (32B rows, XOR swizzle).
// =====================================================================

namespace {
constexpr int Ll = 2048, Dd = 256, Ks = 8, ROWS = 16384;
constexpr int TM   = 128;              // rows per CTA (2 groups x 64)
constexpr int NT   = 256;              // 8 warps
constexpr int NCH  = 16;               // k-chunks of 16
constexpr int WCH  = 8192;             // packed chunk image: 256n x 32B
constexpr int HSTR = 264;              // H/X row stride in halfs (padded)
constexpr int GHSB = 64 * HSTR * 2;    // 33792 bytes per group image
// rnn: per-group ring of 4 single-W slots
constexpr int RRING = 4;
constexpr int SMEMR = 4 * GHSB + 2 * RRING * WCH;      // 200704
constexpr int GTOT  = (Ks - 1) * NCH;                  // 112
// u_gemm: per-group ring of 2 (hi+lo) slots
constexpr int URING = 2;
constexpr int SMEMU = 4 * GHSB + 2 * URING * 2 * WCH;  // 200704
}

__device__ float g_U[ROWS * Dd];
__device__ __align__(16) __half g_Wf[NCH * 4096];    // 16 x 8192 B
__device__ __align__(16) __half g_WIhi[NCH * 4096];
__device__ __align__(16) __half g_WIlo[NCH * 4096];
__device__ float g_itau[Dd];

// ------------------------- PTX helpers --------------------------------
__device__ __forceinline__ uint32_t smem_u32(const void* p) {
    uint32_t a;
    asm("{ .reg .u64 t; cvta.to.shared.u64 t, %1; cvt.u32.u64 %0, t; }"
        : "=r"(a) : "l"(p));
    return a;
}

#define BARG(grp) \
    asm volatile("bar.sync %0, 128;" :: "r"((grp) + 1) : "memory")

#define MBARRIER_INIT(mbar, cnt) \
    asm volatile("mbarrier.init.shared.b64 [%0], %1;" \
                 :: "r"((uint32_t)(mbar)), "r"((uint32_t)(cnt)) : "memory")
#define MBARRIER_ARRIVE(mbar) \
    asm volatile("mbarrier.arrive.shared.b64 _, [%0];" \
                 :: "r"((uint32_t)(mbar)) : "memory")
#define MBARRIER_EXPECT_TX(mbar, bytes) \
    asm volatile("mbarrier.arrive.expect_tx.shared.b64 _, [%0], %1;" \
                 :: "r"((uint32_t)(mbar)), "r"((uint32_t)(bytes)) : "memory")
#define MBARRIER_WAIT_PARITY(mbar, parity) do {                               \
    uint32_t _m = (uint32_t)(mbar);                                           \
    uint32_t _p = (uint32_t)(parity);                                         \
    uint32_t _done;                                                           \
    asm volatile(                                                             \
        "{\n\t.reg .pred p;\n\t"                                              \
        "mbarrier.try_wait.parity.acquire.cta.shared::cta.b64 p, [%1], %2;\n\t" \
        "selp.b32 %0, 1, 0, p;\n\t}"                                          \
        : "=r"(_done) : "r"(_m), "r"(_p) : "memory");                         \
    if (!_done) {                                                             \
        asm volatile(                                                         \
            "{\n\t.reg .pred P1;\n\t"                                         \
            "WL_%=:\n\t"                                                      \
            "mbarrier.try_wait.parity.acquire.cta.shared::cta.b64 P1, [%0], %1, 0x989680;\n\t" \
            "@P1 bra.uni WD_%=;\n\t"                                          \
            "bra.uni WL_%=;\n\t"                                              \
            "WD_%=:\n\t}"                                                     \
            :: "r"(_m), "r"(_p) : "memory");                                  \
    }                                                                         \
} while (0)

#define BULK_G2S(dst, src, bytes, mbar)                                       \
    asm volatile(                                                             \
        "cp.async.bulk.shared::cluster.global.mbarrier::complete_tx::bytes "  \
        "[%0], [%1], %2, [%3];"                                               \
        :: "r"((uint32_t)(dst)), "l"(src), "r"((uint32_t)(bytes)),            \
           "r"((uint32_t)(mbar)) : "memory")

#define LDSM_X4(r, addr)                                                      \
    asm volatile("ldmatrix.sync.aligned.m8n8.x4.shared.b16 "                  \
                 "{%0,%1,%2,%3}, [%4];"                                       \
                 : "=r"((r)[0]), "=r"((r)[1]), "=r"((r)[2]), "=r"((r)[3])     \
                 : "r"(addr))

#define MMAH(d, a, b0_, b1_)                                                  \
    asm volatile(                                                             \
        "mma.sync.aligned.m16n8k16.row.col.f32.f16.f16.f32 "                  \
        "{%0,%1,%2,%3},{%4,%5,%6,%7},{%8,%9},{%0,%1,%2,%3};"                  \
        : "+f"((d)[0]), "+f"((d)[1]), "+f"((d)[2]), "+f"((d)[3])              \
        : "r"((a)[0]), "r"((a)[1]), "r"((a)[2]), "r"((a)[3]),                 \
          "r"(b0_), "r"(b1_))

__device__ __forceinline__ uint32_t pack_hi(float x, float y) {
    __half2 p = __floats2half2_rn(x, y);
    return *(uint32_t*)&p;
}
__device__ __forceinline__ uint32_t pack_lo(float x, float y, uint32_t hi) {
    __half2 h = *(__half2*)&hi;
    __half2 p = __floats2half2_rn(x - __half2float(__low2half(h)),
                                  y - __half2float(__high2half(h)));
    return *(uint32_t*)&p;
}

// ====================== k0: W prep ====================================
// Packed chunk image, 32B rows with XOR swizzle:
// addr(k,n) = (k>>4)*8192 + n*32 + (((k>>3 & 1) ^ (n>>2 & 1))<<4) + (k&7)*2
__global__ void w_prep_kernel(const float* __restrict__ W,
                              const float* __restrict__ Win,
                              const float* __restrict__ tau) {
    int idx = blockIdx.x * blockDim.x + threadIdx.x;  // 0..65535
    int k = idx >> 8, n = idx & 255;
    uint32_t off = (uint32_t)(k >> 4) * 8192u + (uint32_t)n * 32u +
                   ((((uint32_t)(k >> 3) & 1u) ^ ((uint32_t)(n >> 2) & 1u)) << 4) +
                   (uint32_t)(k & 7) * 2u;
    *(__half*)((char*)g_Wf + off) = __float2half_rn(W[k * Dd + n]);
    float wi = Win[k * Dd + n];
    __half hi = __float2half_rn(wi);
    *(__half*)((char*)g_WIhi + off) = hi;
    *(__half*)((char*)g_WIlo + off) = __float2half_rn(wi - __half2float(hi));
    if (idx < Dd) g_itau[idx] = 1.0f / tau[idx];
}

// ====================== k1: U = X @ Win + bias (HMMA, 3-term) =========
__global__ __launch_bounds__(NT, 1) void u_gemm_kernel(const float* __restrict__ X,
                                                       const float* __restrict__ bias) {
    extern __shared__ __align__(128) char dsmem[];
    __shared__ __align__(8) uint64_t s_full[2][URING];
    __shared__ __align__(8) uint64_t s_empty[2][URING];

    const int tid = threadIdx.x;
    const int wid = tid >> 5;
    const int t   = tid & 31;
    const int grp = wid >> 2;
    const int wg  = wid & 3;

    const uint32_t base  = smem_u32(dsmem);
    const uint32_t xs_hi = base + grp * 2 * GHSB;
    const uint32_t xs_lo = xs_hi + GHSB;
    const uint32_t ring  = base + 4 * GHSB + grp * URING * 2 * WCH;
    const uint32_t mbf   = smem_u32(&s_full[grp][0]);
    const uint32_t mbe   = smem_u32(&s_empty[grp][0]);
    const int r0 = blockIdx.x * TM + grp * 64;

    if (tid == 0) {
        for (int gq = 0; gq < 2; gq++)
            for (int i = 0; i < URING; i++) {
                MBARRIER_INIT(smem_u32(&s_full[gq][i]), 1);
                MBARRIER_INIT(smem_u32(&s_empty[gq][i]), 4);
            }
    }
    __syncthreads();

    if (wg == 0 && t == 0) {
#pragma unroll
        for (int s = 0; s < URING; s++) {
            uint32_t sb = ring + s * 2 * WCH;
            MBARRIER_EXPECT_TX(mbf + s * 8, 2 * WCH);
            BULK_G2S(sb,       (const char*)g_WIhi + s * WCH, WCH, mbf + s * 8);
            BULK_G2S(sb + WCH, (const char*)g_WIlo + s * WCH, WCH, mbf + s * 8);
        }
    }

    // ---- load X rows (group-owned), split fp16 hi/lo ----
    for (int rr = wg; rr < 64; rr += 4) {
        const float* xr = X + (size_t)(r0 + rr) * Dd;
#pragma unroll
        for (int half = 0; half < 2; half++) {
            const int c = half * 128 + 4 * t;
            float4 v = *(const float4*)(xr + c);
            uint32_t h0 = pack_hi(v.x, v.y);
            uint32_t h1 = pack_hi(v.z, v.w);
            uint32_t l0 = pack_lo(v.x, v.y, h0);
            uint32_t l1 = pack_lo(v.z, v.w, h1);
            char* hb = dsmem + grp * 2 * GHSB + (size_t)(rr * HSTR + c) * 2;
            *(uint32_t*)(hb)              = h0;
            *(uint32_t*)(hb + 4)          = h1;
            *(uint32_t*)(hb + GHSB)       = l0;
            *(uint32_t*)(hb + GHSB + 4)   = l1;
        }
    }
    BARG(grp);

    const int a_r  = ((t >> 3) & 1) * 8 + (t & 7);
    const int a_k  = ((t >> 4) & 1) * 8;
    const int b_n  = ((t >> 4) & 1) * 8 + (t & 7);
    const int kh   = (t >> 3) & 1;
    const int nbase = wg * 64 + b_n;
    const uint32_t sw16 = ((((uint32_t)nbase >> 2) & 1u) ^ (uint32_t)kh) << 4;

    float D[4][8][4];
#pragma unroll
    for (int i = 0; i < 4; i++)
#pragma unroll
        for (int j = 0; j < 8; j++)
#pragma unroll
            for (int q = 0; q < 4; q++) D[i][j][q] = 0.f;

    for (int g = 0; g < NCH; g++) {
        const int s = g & 1;
        const uint32_t ph = ((uint32_t)g >> 1) & 1u;
        MBARRIER_WAIT_PARITY(mbf + s * 8, ph);

        uint32_t AH[4][4], AL[4][4];
        const int kc = g * 16;
#pragma unroll
        for (int i = 0; i < 4; i++) {
            uint32_t off = (uint32_t)((i * 16 + a_r) * HSTR + kc + a_k) * 2;
            LDSM_X4(AH[i], xs_hi + off);
            LDSM_X4(AL[i], xs_lo + off);
        }
        const uint32_t sb = ring + s * 2 * WCH;
        uint32_t BH[4][4], BL[4][4];
#pragma unroll
        for (int jp = 0; jp < 4; jp++) {
            uint32_t ba = sb + (uint32_t)(nbase + jp * 16) * 32 + sw16;
            LDSM_X4(BH[jp], ba);
            LDSM_X4(BL[jp], ba + WCH);
        }
        __syncwarp();
        if (t == 0) MBARRIER_ARRIVE(mbe + s * 8);

#pragma unroll
        for (int jp = 0; jp < 4; jp++)
#pragma unroll
            for (int i = 0; i < 4; i++) {
                MMAH(D[i][2 * jp],     AH[i], BH[jp][0], BH[jp][1]);
                MMAH(D[i][2 * jp],     AL[i], BH[jp][0], BH[jp][1]);
                MMAH(D[i][2 * jp],     AH[i], BL[jp][0], BL[jp][1]);
                MMAH(D[i][2 * jp + 1], AH[i], BH[jp][2], BH[jp][3]);
                MMAH(D[i][2 * jp + 1], AL[i], BH[jp][2], BH[jp][3]);
                MMAH(D[i][2 * jp + 1], AH[i], BL[jp][2], BL[jp][3]);
            }

        if (wg == 0 && t == 0 && g + URING < NCH) {
            MBARRIER_WAIT_PARITY(mbe + s * 8, ph);
            const int cp = g + URING;
            uint32_t sb2 = ring + s * 2 * WCH;
            MBARRIER_EXPECT_TX(mbf + s * 8, 2 * WCH);
            BULK_G2S(sb2,       (const char*)g_WIhi + cp * WCH, WCH, mbf + s * 8);
            BULK_G2S(sb2 + WCH, (const char*)g_WIlo + cp * WCH, WCH, mbf + s * 8);
        }
    }

    // ---- epilogue: U = D + bias ----
#pragma unroll
    for (int i = 0; i < 4; i++) {
#pragma unroll
        for (int half = 0; half < 2; half++) {
            const int rl = i * 16 + (t >> 2) + half * 8;
            const int gr = r0 + rl;
#pragma unroll
            for (int j = 0; j < 8; j++) {
                const int cc = wg * 64 + j * 8 + 2 * (t & 3);
                float2 b = *(const float2*)(bias + cc);
                *(float2*)(g_U + (size_t)gr * Dd + cc) =
                    make_float2(D[i][j][half * 2] + b.x,
                                D[i][j][half * 2 + 1] + b.y);
            }
        }
    }
}

// ====================== k2: fused HMMA RNN (fp16 2-term) ==============
__global__ __launch_bounds__(NT, 1) void rnn_kernel(const float* __restrict__ bias,
                                                    float* __restrict__ out) {
    extern __shared__ __align__(128) char dsmem[];
    __shared__ __align__(8) uint64_t s_full[2][RRING];
    __shared__ __align__(8) uint64_t s_empty[2][RRING];

    const int tid = threadIdx.x;
    const int wid = tid >> 5;
    const int t   = tid & 31;
    const int grp = wid >> 2;
    const int wg  = wid & 3;

    const uint32_t base  = smem_u32(dsmem);
    const uint32_t hs_hi = base + grp * 2 * GHSB;
    const uint32_t hs_lo = hs_hi + GHSB;
    const uint32_t ring  = base + 4 * GHSB + grp * RRING * WCH;
    const uint32_t mbf   = smem_u32(&s_full[grp][0]);
    const uint32_t mbe   = smem_u32(&s_empty[grp][0]);
    const int r0 = blockIdx.x * TM + grp * 64;

    if (tid == 0) {
        for (int gq = 0; gq < 2; gq++)
            for (int i = 0; i < RRING; i++) {
                MBARRIER_INIT(smem_u32(&s_full[gq][i]), 1);
                MBARRIER_INIT(smem_u32(&s_empty[gq][i]), 4);
            }
    }
    __syncthreads();

    if (wg == 0 && t == 0) {
#pragma unroll
        for (int s = 0; s < RRING; s++) {
            MBARRIER_EXPECT_TX(mbf + s * 8, WCH);
            BULK_G2S(ring + s * WCH, (const char*)g_Wf + s * WCH, WCH,
                     mbf + s * 8);
        }
    }

    // ---- step 0: h1 = itau * relu(u_{l-7}) ----
    for (int rr = wg; rr < 64; rr += 4) {
        const int gr = r0 + rr;
        const int l  = gr & (Ll - 1);
        const float* us = (l >= Ks - 1) ? g_U + (size_t)(gr - (Ks - 1)) * Dd
                                        : bias;
#pragma unroll
        for (int half = 0; half < 2; half++) {
            const int c = half * 128 + 4 * t;
            float4 v  = *(const float4*)(us + c);
            float4 it = *(const float4*)(g_itau + c);
            float h0 = it.x * fmaxf(v.x, 0.f);
            float h1 = it.y * fmaxf(v.y, 0.f);
            float h2 = it.z * fmaxf(v.z, 0.f);
            float h3 = it.w * fmaxf(v.w, 0.f);
            uint32_t p0 = pack_hi(h0, h1);
            uint32_t p1 = pack_hi(h2, h3);
            uint32_t q0 = pack_lo(h0, h1, p0);
            uint32_t q1 = pack_lo(h2, h3, p1);
            char* hb = dsmem + grp * 2 * GHSB + (size_t)(rr * HSTR + c) * 2;
            *(uint32_t*)(hb)            = p0;
            *(uint32_t*)(hb + 4)        = p1;
            *(uint32_t*)(hb + GHSB)     = q0;
            *(uint32_t*)(hb + GHSB + 4) = q1;
        }
    }
    BARG(grp);

    const int a_r  = ((t >> 3) & 1) * 8 + (t & 7);
    const int a_k  = ((t >> 4) & 1) * 8;
    const int b_n  = ((t >> 4) & 1) * 8 + (t & 7);
    const int kh   = (t >> 3) & 1;
    const int nbase = wg * 64 + b_n;
    const uint32_t sw16 = ((((uint32_t)nbase >> 2) & 1u) ^ (uint32_t)kh) << 4;

    int g = 0;
    for (int step = 1; step < Ks; step++) {
        float D[4][8][4];
#pragma unroll
        for (int i = 0; i < 4; i++)
#pragma unroll
            for (int j = 0; j < 8; j++)
#pragma unroll
                for (int q = 0; q < 4; q++) D[i][j][q] = 0.f;

        for (int c = 0; c < NCH; c++, g++) {
            const int s = g & 3;
            const uint32_t ph = ((uint32_t)g >> 2) & 1u;
            MBARRIER_WAIT_PARITY(mbf + s * 8, ph);

            uint32_t AH[4][4], AL[4][4];
            const int kc = c * 16;
#pragma unroll
            for (int i = 0; i < 4; i++) {
                uint32_t off = (uint32_t)((i * 16 + a_r) * HSTR + kc + a_k) * 2;
                LDSM_X4(AH[i], hs_hi + off);
                LDSM_X4(AL[i], hs_lo + off);
            }
            const uint32_t sb = ring + s * WCH;
            uint32_t BH[4][4];
#pragma unroll
            for (int jp = 0; jp < 4; jp++)
                LDSM_X4(BH[jp], sb + (uint32_t)(nbase + jp * 16) * 32 + sw16);
            __syncwarp();
            if (t == 0) MBARRIER_ARRIVE(mbe + s * 8);

#pragma unroll
            for (int jp = 0; jp < 4; jp++)
#pragma unroll
                for (int i = 0; i < 4; i++) {
                    MMAH(D[i][2 * jp],     AH[i], BH[jp][0], BH[jp][1]);
                    MMAH(D[i][2 * jp],     AL[i], BH[jp][0], BH[jp][1]);
                    MMAH(D[i][2 * jp + 1], AH[i], BH[jp][2], BH[jp][3]);
                    MMAH(D[i][2 * jp + 1], AL[i], BH[jp][2], BH[jp][3]);
                }

            if (wg == 0 && t == 0 && g + RRING < GTOT) {
                MBARRIER_WAIT_PARITY(mbe + s * 8, ph);
                const int cp = (g + RRING) & 15;
                MBARRIER_EXPECT_TX(mbf + s * 8, WCH);
                BULK_G2S(ring + s * WCH, (const char*)g_Wf + cp * WCH, WCH,
                         mbf + s * 8);
            }
        }
        BARG(grp);   // all A-reads of this group's Hs done before writes

        // ---- fused epilogue: h' = h + itau*(relu(D+u) - h) ----
        const bool last = (step == Ks - 1);
#pragma unroll
        for (int i = 0; i < 4; i++) {
#pragma unroll
            for (int half = 0; half < 2; half++) {
                const int rl = i * 16 + (t >> 2) + half * 8;
                const int gr = r0 + rl;
                const int tt = (gr & (Ll - 1)) - (Ks - 1) + step;
                const float* us = (tt >= 0)
                    ? g_U + (size_t)(gr - (Ks - 1) + step) * Dd : bias;
#pragma unroll
                for (int j = 0; j < 8; j++) {
                    const int cc = wg * 64 + j * 8 + 2 * (t & 3);
                    float2 u  = *(const float2*)(us + cc);
                    float2 it = *(const float2*)(g_itau + cc);
                    const float d0 = D[i][j][half * 2];
                    const float d1 = D[i][j][half * 2 + 1];
                    char* hb = dsmem + grp * 2 * GHSB +
                               (size_t)(rl * HSTR + cc) * 2;
                    uint32_t hv = *(uint32_t*)(hb);
                    uint32_t lv = *(uint32_t*)(hb + GHSB);
                    __half2 hh = *(__half2*)&hv;
                    __half2 ll = *(__half2*)&lv;
                    float h0 = __half2float(__low2half(hh)) +
                               __half2float(__low2half(ll));
                    float h1 = __half2float(__high2half(hh)) +
                               __half2float(__high2half(ll));
                    float s0 = fmaxf(d0 + u.x, 0.f);
                    float s1 = fmaxf(d1 + u.y, 0.f);
                    float n0 = h0 + it.x * (s0 - h0);
                    float n1 = h1 + it.y * (s1 - h1);
                    if (last) {
                        *(float2*)(out + (size_t)gr * Dd + cc) =
                            make_float2(n0, n1);
                    } else {
                        uint32_t hi = pack_hi(n0, n1);
                        uint32_t lo = pack_lo(n0, n1, hi);
                        *(uint32_t*)(hb)        = hi;
                        *(uint32_t*)(hb + GHSB) = lo;
                    }
                }
            }
        }
        if (!last) BARG(grp);
    }
}

// ---------------------------------------------------------------------------
extern "C" void kernel_launch(void* const* d_in, const int* in_sizes, int n_in,
                              void* d_out, int out_size) {
    (void)in_sizes; (void)n_in; (void)out_size;
    const float* x            = (const float*)d_in[0];
    const float* weight       = (const float*)d_in[1];
    const float* input_weight = (const float*)d_in[2];
    const float* bias         = (const float*)d_in[3];
    const float* tau          = (const float*)d_in[4];
    float* out = (float*)d_out;

    w_prep_kernel<<<Dd * Dd / 256, 256>>>(weight, input_weight, tau);

    cudaFuncSetAttribute(u_gemm_kernel, cudaFuncAttributeMaxDynamicSharedMemorySize,
                         SMEMU);
    u_gemm_kernel<<<ROWS / TM, NT, SMEMU>>>(x, bias);

    cudaFuncSetAttribute(rnn_kernel, cudaFuncAttributeMaxDynamicSharedMemorySize,
                         SMEMR);
    rnn_kernel<<<ROWS / TM, NT, SMEMR>>>(bias, out);
}

// round 6
// speedup vs baseline: 4.5812x; 1.3116x over previous
#include <cuda_runtime.h>
#include <cuda_fp16.h>
#include <cstdint>

// =====================================================================
// LocalRNN: B=8, L=2048, D=256, KSIZE=8   (sm_103 portable HMMA path)
// R6: rnn uses SINGLE fp16 H (MMA count halved — kernel is MMA-issue
//     bound per R5 post-mortem). Shared 12-slot W ring for both 64-row
//     groups (halved L2 traffic, deeper pipeline). U stays 3-term exact.
// =====================================================================

namespace {
constexpr int Ll = 2048, Dd = 256, Ks = 8, ROWS = 16384;
constexpr int TM   = 128;              // rows per CTA (2 groups x 64)
constexpr int NT   = 256;              // 8 warps
constexpr int NCH  = 16;               // k-chunks of 16
constexpr int WCH  = 8192;             // packed chunk image: 256n x 32B
constexpr int HSTR = 264;              // H/X row stride in halfs (padded)
constexpr int GHSB = 64 * HSTR * 2;    // 33792 bytes per group image
// rnn: ONE shared ring of 12 W slots; single H image per group
constexpr int RRING = 12;
constexpr int SMEMR = 2 * GHSB + RRING * WCH;          // 165888
constexpr int GTOT  = (Ks - 1) * NCH;                  // 112
// u_gemm: per-group ring of 2 (hi+lo) slots; X hi/lo images per group
constexpr int URING = 2;
constexpr int SMEMU = 4 * GHSB + 2 * URING * 2 * WCH;  // 200704
}

__device__ float g_U[ROWS * Dd];
__device__ __align__(16) __half g_Wf[NCH * 4096];    // 16 x 8192 B
__device__ __align__(16) __half g_WIhi[NCH * 4096];
__device__ __align__(16) __half g_WIlo[NCH * 4096];
__device__ float g_itau[Dd];

// ------------------------- PTX helpers --------------------------------
__device__ __forceinline__ uint32_t smem_u32(const void* p) {
    uint32_t a;
    asm("{ .reg .u64 t; cvta.to.shared.u64 t, %1; cvt.u32.u64 %0, t; }"
        : "=r"(a) : "l"(p));
    return a;
}

#define BARG(grp) \
    asm volatile("bar.sync %0, 128;" :: "r"((grp) + 1) : "memory")

#define MBARRIER_INIT(mbar, cnt) \
    asm volatile("mbarrier.init.shared.b64 [%0], %1;" \
                 :: "r"((uint32_t)(mbar)), "r"((uint32_t)(cnt)) : "memory")
#define MBARRIER_ARRIVE(mbar) \
    asm volatile("mbarrier.arrive.shared.b64 _, [%0];" \
                 :: "r"((uint32_t)(mbar)) : "memory")
#define MBARRIER_EXPECT_TX(mbar, bytes) \
    asm volatile("mbarrier.arrive.expect_tx.shared.b64 _, [%0], %1;" \
                 :: "r"((uint32_t)(mbar)), "r"((uint32_t)(bytes)) : "memory")
#define MBARRIER_WAIT_PARITY(mbar, parity) do {                               \
    uint32_t _m = (uint32_t)(mbar);                                           \
    uint32_t _p = (uint32_t)(parity);                                         \
    uint32_t _done;                                                           \
    asm volatile(                                                             \
        "{\n\t.reg .pred p;\n\t"                                              \
        "mbarrier.try_wait.parity.acquire.cta.shared::cta.b64 p, [%1], %2;\n\t" \
        "selp.b32 %0, 1, 0, p;\n\t}"                                          \
        : "=r"(_done) : "r"(_m), "r"(_p) : "memory");                         \
    if (!_done) {                                                             \
        asm volatile(                                                         \
            "{\n\t.reg .pred P1;\n\t"                                         \
            "WL_%=:\n\t"                                                      \
            "mbarrier.try_wait.parity.acquire.cta.shared::cta.b64 P1, [%0], %1, 0x989680;\n\t" \
            "@P1 bra.uni WD_%=;\n\t"                                          \
            "bra.uni WL_%=;\n\t"                                              \
            "WD_%=:\n\t}"                                                     \
            :: "r"(_m), "r"(_p) : "memory");                                  \
    }                                                                         \
} while (0)

#define BULK_G2S(dst, src, bytes, mbar)                                       \
    asm volatile(                                                             \
        "cp.async.bulk.shared::cluster.global.mbarrier::complete_tx::bytes "  \
        "[%0], [%1], %2, [%3];"                                               \
        :: "r"((uint32_t)(dst)), "l"(src), "r"((uint32_t)(bytes)),            \
           "r"((uint32_t)(mbar)) : "memory")

#define LDSM_X4(r, addr)                                                      \
    asm volatile("ldmatrix.sync.aligned.m8n8.x4.shared.b16 "                  \
                 "{%0,%1,%2,%3}, [%4];"                                       \
                 : "=r"((r)[0]), "=r"((r)[1]), "=r"((r)[2]), "=r"((r)[3])     \
                 : "r"(addr))

#define MMAH(d, a, b0_, b1_)                                                  \
    asm volatile(                                                             \
        "mma.sync.aligned.m16n8k16.row.col.f32.f16.f16.f32 "                  \
        "{%0,%1,%2,%3},{%4,%5,%6,%7},{%8,%9},{%0,%1,%2,%3};"                  \
        : "+f"((d)[0]), "+f"((d)[1]), "+f"((d)[2]), "+f"((d)[3])              \
        : "r"((a)[0]), "r"((a)[1]), "r"((a)[2]), "r"((a)[3]),                 \
          "r"(b0_), "r"(b1_))

__device__ __forceinline__ uint32_t pack_hi(float x, float y) {
    __half2 p = __floats2half2_rn(x, y);
    return *(uint32_t*)&p;
}
__device__ __forceinline__ uint32_t pack_lo(float x, float y, uint32_t hi) {
    __half2 h = *(__half2*)&hi;
    __half2 p = __floats2half2_rn(x - __half2float(__low2half(h)),
                                  y - __half2float(__high2half(h)));
    return *(uint32_t*)&p;
}

// ====================== k0: W prep ====================================
// Packed chunk image, 32B rows with XOR swizzle:
// addr(k,n) = (k>>4)*8192 + n*32 + (((k>>3 & 1) ^ (n>>2 & 1))<<4) + (k&7)*2
__global__ void w_prep_kernel(const float* __restrict__ W,
                              const float* __restrict__ Win,
                              const float* __restrict__ tau) {
    int idx = blockIdx.x * blockDim.x + threadIdx.x;  // 0..65535
    int k = idx >> 8, n = idx & 255;
    uint32_t off = (uint32_t)(k >> 4) * 8192u + (uint32_t)n * 32u +
                   ((((uint32_t)(k >> 3) & 1u) ^ ((uint32_t)(n >> 2) & 1u)) << 4) +
                   (uint32_t)(k & 7) * 2u;
    *(__half*)((char*)g_Wf + off) = __float2half_rn(W[k * Dd + n]);
    float wi = Win[k * Dd + n];
    __half hi = __float2half_rn(wi);
    *(__half*)((char*)g_WIhi + off) = hi;
    *(__half*)((char*)g_WIlo + off) = __float2half_rn(wi - __half2float(hi));
    if (idx < Dd) g_itau[idx] = 1.0f / tau[idx];
}

// ====================== k1: U = X @ Win + bias (HMMA, 3-term) =========
__global__ __launch_bounds__(NT, 1) void u_gemm_kernel(const float* __restrict__ X,
                                                       const float* __restrict__ bias) {
    extern __shared__ __align__(128) char dsmem[];
    __shared__ __align__(8) uint64_t s_full[2][URING];
    __shared__ __align__(8) uint64_t s_empty[2][URING];

    const int tid = threadIdx.x;
    const int wid = tid >> 5;
    const int t   = tid & 31;
    const int grp = wid >> 2;
    const int wg  = wid & 3;

    const uint32_t base  = smem_u32(dsmem);
    const uint32_t xs_hi = base + grp * 2 * GHSB;
    const uint32_t xs_lo = xs_hi + GHSB;
    const uint32_t ring  = base + 4 * GHSB + grp * URING * 2 * WCH;
    const uint32_t mbf   = smem_u32(&s_full[grp][0]);
    const uint32_t mbe   = smem_u32(&s_empty[grp][0]);
    const int r0 = blockIdx.x * TM + grp * 64;

    if (tid == 0) {
        for (int gq = 0; gq < 2; gq++)
            for (int i = 0; i < URING; i++) {
                MBARRIER_INIT(smem_u32(&s_full[gq][i]), 1);
                MBARRIER_INIT(smem_u32(&s_empty[gq][i]), 4);
            }
    }
    __syncthreads();

    if (wg == 0 && t == 0) {
#pragma unroll
        for (int s = 0; s < URING; s++) {
            uint32_t sb = ring + s * 2 * WCH;
            MBARRIER_EXPECT_TX(mbf + s * 8, 2 * WCH);
            BULK_G2S(sb,       (const char*)g_WIhi + s * WCH, WCH, mbf + s * 8);
            BULK_G2S(sb + WCH, (const char*)g_WIlo + s * WCH, WCH, mbf + s * 8);
        }
    }

    // ---- load X rows (group-owned), split fp16 hi/lo ----
    for (int rr = wg; rr < 64; rr += 4) {
        const float* xr = X + (size_t)(r0 + rr) * Dd;
#pragma unroll
        for (int half = 0; half < 2; half++) {
            const int c = half * 128 + 4 * t;
            float4 v = *(const float4*)(xr + c);
            uint32_t h0 = pack_hi(v.x, v.y);
            uint32_t h1 = pack_hi(v.z, v.w);
            uint32_t l0 = pack_lo(v.x, v.y, h0);
            uint32_t l1 = pack_lo(v.z, v.w, h1);
            char* hb = dsmem + grp * 2 * GHSB + (size_t)(rr * HSTR + c) * 2;
            *(uint32_t*)(hb)              = h0;
            *(uint32_t*)(hb + 4)          = h1;
            *(uint32_t*)(hb + GHSB)       = l0;
            *(uint32_t*)(hb + GHSB + 4)   = l1;
        }
    }
    BARG(grp);

    const int a_r  = ((t >> 3) & 1) * 8 + (t & 7);
    const int a_k  = ((t >> 4) & 1) * 8;
    const int b_n  = ((t >> 4) & 1) * 8 + (t & 7);
    const int kh   = (t >> 3) & 1;
    const int nbase = wg * 64 + b_n;
    const uint32_t sw16 = ((((uint32_t)nbase >> 2) & 1u) ^ (uint32_t)kh) << 4;

    float D[4][8][4];
#pragma unroll
    for (int i = 0; i < 4; i++)
#pragma unroll
        for (int j = 0; j < 8; j++)
#pragma unroll
            for (int q = 0; q < 4; q++) D[i][j][q] = 0.f;

    for (int g = 0; g < NCH; g++) {
        const int s = g & 1;
        const uint32_t ph = ((uint32_t)g >> 1) & 1u;
        MBARRIER_WAIT_PARITY(mbf + s * 8, ph);

        uint32_t AH[4][4], AL[4][4];
        const int kc = g * 16;
#pragma unroll
        for (int i = 0; i < 4; i++) {
            uint32_t off = (uint32_t)((i * 16 + a_r) * HSTR + kc + a_k) * 2;
            LDSM_X4(AH[i], xs_hi + off);
            LDSM_X4(AL[i], xs_lo + off);
        }
        const uint32_t sb = ring + s * 2 * WCH;
        uint32_t BH[4][4], BL[4][4];
#pragma unroll
        for (int jp = 0; jp < 4; jp++) {
            uint32_t ba = sb + (uint32_t)(nbase + jp * 16) * 32 + sw16;
            LDSM_X4(BH[jp], ba);
            LDSM_X4(BL[jp], ba + WCH);
        }
        __syncwarp();
        if (t == 0) MBARRIER_ARRIVE(mbe + s * 8);

#pragma unroll
        for (int jp = 0; jp < 4; jp++)
#pragma unroll
            for (int i = 0; i < 4; i++) {
                MMAH(D[i][2 * jp],     AH[i], BH[jp][0], BH[jp][1]);
                MMAH(D[i][2 * jp],     AL[i], BH[jp][0], BH[jp][1]);
                MMAH(D[i][2 * jp],     AH[i], BL[jp][0], BL[jp][1]);
                MMAH(D[i][2 * jp + 1], AH[i], BH[jp][2], BH[jp][3]);
                MMAH(D[i][2 * jp + 1], AL[i], BH[jp][2], BH[jp][3]);
                MMAH(D[i][2 * jp + 1], AH[i], BL[jp][2], BL[jp][3]);
            }

        if (wg == 0 && t == 0 && g + URING < NCH) {
            MBARRIER_WAIT_PARITY(mbe + s * 8, ph);
            const int cp = g + URING;
            uint32_t sb2 = ring + s * 2 * WCH;
            MBARRIER_EXPECT_TX(mbf + s * 8, 2 * WCH);
            BULK_G2S(sb2,       (const char*)g_WIhi + cp * WCH, WCH, mbf + s * 8);
            BULK_G2S(sb2 + WCH, (const char*)g_WIlo + cp * WCH, WCH, mbf + s * 8);
        }
    }

    // ---- epilogue: U = D + bias ----
#pragma unroll
    for (int i = 0; i < 4; i++) {
#pragma unroll
        for (int half = 0; half < 2; half++) {
            const int rl = i * 16 + (t >> 2) + half * 8;
            const int gr = r0 + rl;
#pragma unroll
            for (int j = 0; j < 8; j++) {
                const int cc = wg * 64 + j * 8 + 2 * (t & 3);
                float2 b = *(const float2*)(bias + cc);
                *(float2*)(g_U + (size_t)gr * Dd + cc) =
                    make_float2(D[i][j][half * 2] + b.x,
                                D[i][j][half * 2 + 1] + b.y);
            }
        }
    }
}

// ====================== k2: fused HMMA RNN (single fp16 H) ============
__global__ __launch_bounds__(NT, 1) void rnn_kernel(const float* __restrict__ bias,
                                                    float* __restrict__ out) {
    extern __shared__ __align__(128) char dsmem[];
    __shared__ __align__(8) uint64_t s_full[RRING];
    __shared__ __align__(8) uint64_t s_empty[RRING];

    const int tid = threadIdx.x;
    const int wid = tid >> 5;
    const int t   = tid & 31;
    const int grp = wid >> 2;
    const int wg  = wid & 3;

    const uint32_t base  = smem_u32(dsmem);
    const uint32_t hs    = base + grp * GHSB;        // single H image
    const uint32_t ring  = base + 2 * GHSB;          // shared 12-slot ring
    const uint32_t mbf   = smem_u32(s_full);
    const uint32_t mbe   = smem_u32(s_empty);
    const int r0 = blockIdx.x * TM + grp * 64;

    if (tid == 0) {
        for (int i = 0; i < RRING; i++) {
            MBARRIER_INIT(mbf + i * 8, 1);
            MBARRIER_INIT(mbe + i * 8, 8);   // all 8 warps arrive per use
        }
    }
    __syncthreads();

    // Prime all 12 slots with chunks 0..11
    if (tid == 0) {
#pragma unroll
        for (int s = 0; s < RRING; s++) {
            MBARRIER_EXPECT_TX(mbf + s * 8, WCH);
            BULK_G2S(ring + s * WCH, (const char*)g_Wf + s * WCH, WCH,
                     mbf + s * 8);
        }
    }

    // ---- step 0: h1 = itau * relu(u_{l-7}) ----
    for (int rr = wg; rr < 64; rr += 4) {
        const int gr = r0 + rr;
        const int l  = gr & (Ll - 1);
        const float* us = (l >= Ks - 1) ? g_U + (size_t)(gr - (Ks - 1)) * Dd
                                        : bias;
#pragma unroll
        for (int half = 0; half < 2; half++) {
            const int c = half * 128 + 4 * t;
            float4 v  = *(const float4*)(us + c);
            float4 it = *(const float4*)(g_itau + c);
            uint32_t p0 = pack_hi(it.x * fmaxf(v.x, 0.f),
                                  it.y * fmaxf(v.y, 0.f));
            uint32_t p1 = pack_hi(it.z * fmaxf(v.z, 0.f),
                                  it.w * fmaxf(v.w, 0.f));
            char* hb = dsmem + grp * GHSB + (size_t)(rr * HSTR + c) * 2;
            *(uint32_t*)(hb)     = p0;
            *(uint32_t*)(hb + 4) = p1;
        }
    }
    BARG(grp);

    const int a_r  = ((t >> 3) & 1) * 8 + (t & 7);
    const int a_k  = ((t >> 4) & 1) * 8;
    const int b_n  = ((t >> 4) & 1) * 8 + (t & 7);
    const int kh   = (t >> 3) & 1;
    const int nbase = wg * 64 + b_n;
    const uint32_t sw16 = ((((uint32_t)nbase >> 2) & 1u) ^ (uint32_t)kh) << 4;

    int g = 0;
    for (int step = 1; step < Ks; step++) {
        float D[4][8][4];
#pragma unroll
        for (int i = 0; i < 4; i++)
#pragma unroll
            for (int j = 0; j < 8; j++)
#pragma unroll
                for (int q = 0; q < 4; q++) D[i][j][q] = 0.f;

        for (int c = 0; c < NCH; c++, g++) {
            const uint32_t uu = (uint32_t)g / RRING;
            const int s = g - uu * RRING;
            const uint32_t ph = uu & 1u;
            MBARRIER_WAIT_PARITY(mbf + s * 8, ph);

            uint32_t AH[4][4];
            const int kc = c * 16;
#pragma unroll
            for (int i = 0; i < 4; i++) {
                uint32_t off = (uint32_t)((i * 16 + a_r) * HSTR + kc + a_k) * 2;
                LDSM_X4(AH[i], hs + off);
            }
            const uint32_t sb = ring + s * WCH;
            uint32_t BH[4][4];
#pragma unroll
            for (int jp = 0; jp < 4; jp++)
                LDSM_X4(BH[jp], sb + (uint32_t)(nbase + jp * 16) * 32 + sw16);
            __syncwarp();
            if (t == 0) MBARRIER_ARRIVE(mbe + s * 8);

#pragma unroll
            for (int jp = 0; jp < 4; jp++)
#pragma unroll
                for (int i = 0; i < 4; i++) {
                    MMAH(D[i][2 * jp],     AH[i], BH[jp][0], BH[jp][1]);
                    MMAH(D[i][2 * jp + 1], AH[i], BH[jp][2], BH[jp][3]);
                }

            // single producer (tid 0): refill slot s with chunk g+RRING
            if (tid == 0 && g + RRING < GTOT) {
                MBARRIER_WAIT_PARITY(mbe + s * 8, ph);
                const int cp = (g + RRING) & 15;
                MBARRIER_EXPECT_TX(mbf + s * 8, WCH);
                BULK_G2S(ring + s * WCH, (const char*)g_Wf + cp * WCH, WCH,
                         mbf + s * 8);
            }
        }
        BARG(grp);   // all A-reads of this group's Hs done before writes

        // ---- fused epilogue: h' = h + itau*(relu(D+u) - h) ----
        const bool last = (step == Ks - 1);
#pragma unroll
        for (int i = 0; i < 4; i++) {
#pragma unroll
            for (int half = 0; half < 2; half++) {
                const int rl = i * 16 + (t >> 2) + half * 8;
                const int gr = r0 + rl;
                const int tt = (gr & (Ll - 1)) - (Ks - 1) + step;
                const float* us = (tt >= 0)
                    ? g_U + (size_t)(gr - (Ks - 1) + step) * Dd : bias;
#pragma unroll
                for (int j = 0; j < 8; j++) {
                    const int cc = wg * 64 + j * 8 + 2 * (t & 3);
                    float2 u  = *(const float2*)(us + cc);
                    float2 it = *(const float2*)(g_itau + cc);
                    const float d0 = D[i][j][half * 2];
                    const float d1 = D[i][j][half * 2 + 1];
                    char* hb = dsmem + grp * GHSB +
                               (size_t)(rl * HSTR + cc) * 2;
                    uint32_t hv = *(uint32_t*)(hb);
                    __half2 hh = *(__half2*)&hv;
                    float h0 = __half2float(__low2half(hh));
                    float h1 = __half2float(__high2half(hh));
                    float s0 = fmaxf(d0 + u.x, 0.f);
                    float s1 = fmaxf(d1 + u.y, 0.f);
                    float n0 = h0 + it.x * (s0 - h0);
                    float n1 = h1 + it.y * (s1 - h1);
                    if (last) {
                        *(float2*)(out + (size_t)gr * Dd + cc) =
                            make_float2(n0, n1);
                    } else {
                        *(uint32_t*)(hb) = pack_hi(n0, n1);
                    }
                }
            }
        }
        if (!last) BARG(grp);
    }
}

// ---------------------------------------------------------------------------
extern "C" void kernel_launch(void* const* d_in, const int* in_sizes, int n_in,
                              void* d_out, int out_size) {
    (void)in_sizes; (void)n_in; (void)out_size;
    const float* x            = (const float*)d_in[0];
    const float* weight       = (const float*)d_in[1];
    const float* input_weight = (const float*)d_in[2];
    const float* bias         = (const float*)d_in[3];
    const float* tau          = (const float*)d_in[4];
    float* out = (float*)d_out;

    w_prep_kernel<<<Dd * Dd / 256, 256>>>(weight, input_weight, tau);

    cudaFuncSetAttribute(u_gemm_kernel, cudaFuncAttributeMaxDynamicSharedMemorySize,
                         SMEMU);
    u_gemm_kernel<<<ROWS / TM, NT, SMEMU>>>(x, bias);

    cudaFuncSetAttribute(rnn_kernel, cudaFuncAttributeMaxDynamicSharedMemorySize,
                         SMEMR);
    rnn_kernel<<<ROWS / TM, NT, SMEMR>>>(bias, out);
}

// round 7
// speedup vs baseline: 4.6269x; 1.0100x over previous
#include <cuda_runtime.h>
#include <cuda_fp16.h>
#include <cstdint>

// =====================================================================
// LocalRNN: B=8, L=2048, D=256, KSIZE=8   (sm_103 portable HMMA path)
// R7: TM=64 / NT=128 / grid=256 with 2 CTAs per SM -> all 148 SMs busy
//     (was 128/148). Per-CTA: single fp16 H image + shared 8-slot W ring.
//     Numerics identical to R6 (rel_err ~2.3e-4).
// =====================================================================

namespace {
constexpr int Ll = 2048, Dd = 256, Ks = 8, ROWS = 16384;
constexpr int TM   = 64;               // rows per CTA
constexpr int NT   = 128;              // 4 warps
constexpr int NCH  = 16;               // k-chunks of 16
constexpr int WCH  = 8192;             // packed chunk image: 256n x 32B
constexpr int HSTR = 264;              // H/X row stride in halfs (padded)
constexpr int GHSB = TM * HSTR * 2;    // 33792 bytes per image
// rnn: shared ring of 8 single-W slots
constexpr int RRING = 8;
constexpr int SMEMR = GHSB + RRING * WCH;            // 99328  (2 CTAs/SM)
constexpr int GTOT  = (Ks - 1) * NCH;                // 112
// u_gemm: shared ring of 2 (hi+lo) slots; X hi/lo images
constexpr int URING = 2;
constexpr int SMEMU = 2 * GHSB + URING * 2 * WCH;    // 100352 (2 CTAs/SM)
}

__device__ float g_U[ROWS * Dd];
__device__ __align__(16) __half g_Wf[NCH * 4096];    // 16 x 8192 B
__device__ __align__(16) __half g_WIhi[NCH * 4096];
__device__ __align__(16) __half g_WIlo[NCH * 4096];
__device__ float g_itau[Dd];

// ------------------------- PTX helpers --------------------------------
__device__ __forceinline__ uint32_t smem_u32(const void* p) {
    uint32_t a;
    asm("{ .reg .u64 t; cvta.to.shared.u64 t, %1; cvt.u32.u64 %0, t; }"
        : "=r"(a) : "l"(p));
    return a;
}

#define MBARRIER_INIT(mbar, cnt) \
    asm volatile("mbarrier.init.shared.b64 [%0], %1;" \
                 :: "r"((uint32_t)(mbar)), "r"((uint32_t)(cnt)) : "memory")
#define MBARRIER_ARRIVE(mbar) \
    asm volatile("mbarrier.arrive.shared.b64 _, [%0];" \
                 :: "r"((uint32_t)(mbar)) : "memory")
#define MBARRIER_EXPECT_TX(mbar, bytes) \
    asm volatile("mbarrier.arrive.expect_tx.shared.b64 _, [%0], %1;" \
                 :: "r"((uint32_t)(mbar)), "r"((uint32_t)(bytes)) : "memory")
#define MBARRIER_WAIT_PARITY(mbar, parity) do {                               \
    uint32_t _m = (uint32_t)(mbar);                                           \
    uint32_t _p = (uint32_t)(parity);                                         \
    uint32_t _done;                                                           \
    asm volatile(                                                             \
        "{\n\t.reg .pred p;\n\t"                                              \
        "mbarrier.try_wait.parity.acquire.cta.shared::cta.b64 p, [%1], %2;\n\t" \
        "selp.b32 %0, 1, 0, p;\n\t}"                                          \
        : "=r"(_done) : "r"(_m), "r"(_p) : "memory");                         \
    if (!_done) {                                                             \
        asm volatile(                                                         \
            "{\n\t.reg .pred P1;\n\t"                                         \
            "WL_%=:\n\t"                                                      \
            "mbarrier.try_wait.parity.acquire.cta.shared::cta.b64 P1, [%0], %1, 0x989680;\n\t" \
            "@P1 bra.uni WD_%=;\n\t"                                          \
            "bra.uni WL_%=;\n\t"                                              \
            "WD_%=:\n\t}"                                                     \
            :: "r"(_m), "r"(_p) : "memory");                                  \
    }                                                                         \
} while (0)

#define BULK_G2S(dst, src, bytes, mbar)                                       \
    asm volatile(                                                             \
        "cp.async.bulk.shared::cluster.global.mbarrier::complete_tx::bytes "  \
        "[%0], [%1], %2, [%3];"                                               \
        :: "r"((uint32_t)(dst)), "l"(src), "r"((uint32_t)(bytes)),            \
           "r"((uint32_t)(mbar)) : "memory")

#define LDSM_X4(r, addr)                                                      \
    asm volatile("ldmatrix.sync.aligned.m8n8.x4.shared.b16 "                  \
                 "{%0,%1,%2,%3}, [%4];"                                       \
                 : "=r"((r)[0]), "=r"((r)[1]), "=r"((r)[2]), "=r"((r)[3])     \
                 : "r"(addr))

#define MMAH(d, a, b0_, b1_)                                                  \
    asm volatile(                                                             \
        "mma.sync.aligned.m16n8k16.row.col.f32.f16.f16.f32 "                  \
        "{%0,%1,%2,%3},{%4,%5,%6,%7},{%8,%9},{%0,%1,%2,%3};"                  \
        : "+f"((d)[0]), "+f"((d)[1]), "+f"((d)[2]), "+f"((d)[3])              \
        : "r"((a)[0]), "r"((a)[1]), "r"((a)[2]), "r"((a)[3]),                 \
          "r"(b0_), "r"(b1_))

__device__ __forceinline__ uint32_t pack_hi(float x, float y) {
    __half2 p = __floats2half2_rn(x, y);
    return *(uint32_t*)&p;
}
__device__ __forceinline__ uint32_t pack_lo(float x, float y, uint32_t hi) {
    __half2 h = *(__half2*)&hi;
    __half2 p = __floats2half2_rn(x - __half2float(__low2half(h)),
                                  y - __half2float(__high2half(h)));
    return *(uint32_t*)&p;
}

// ====================== k0: W prep ====================================
// Packed chunk image, 32B rows with XOR swizzle:
// addr(k,n) = (k>>4)*8192 + n*32 + (((k>>3 & 1) ^ (n>>2 & 1))<<4) + (k&7)*2
__global__ void w_prep_kernel(const float* __restrict__ W,
                              const float* __restrict__ Win,
                              const float* __restrict__ tau) {
    int idx = blockIdx.x * blockDim.x + threadIdx.x;  // 0..65535
    int k = idx >> 8, n = idx & 255;
    uint32_t off = (uint32_t)(k >> 4) * 8192u + (uint32_t)n * 32u +
                   ((((uint32_t)(k >> 3) & 1u) ^ ((uint32_t)(n >> 2) & 1u)) << 4) +
                   (uint32_t)(k & 7) * 2u;
    *(__half*)((char*)g_Wf + off) = __float2half_rn(W[k * Dd + n]);
    float wi = Win[k * Dd + n];
    __half hi = __float2half_rn(wi);
    *(__half*)((char*)g_WIhi + off) = hi;
    *(__half*)((char*)g_WIlo + off) = __float2half_rn(wi - __half2float(hi));
    if (idx < Dd) g_itau[idx] = 1.0f / tau[idx];
}

// ====================== k1: U = X @ Win + bias (HMMA, 3-term) =========
__global__ __launch_bounds__(NT, 2) void u_gemm_kernel(const float* __restrict__ X,
                                                       const float* __restrict__ bias) {
    extern __shared__ __align__(128) char dsmem[];
    __shared__ __align__(8) uint64_t s_full[URING];
    __shared__ __align__(8) uint64_t s_empty[URING];

    const int tid = threadIdx.x;
    const int wid = tid >> 5;
    const int t   = tid & 31;

    const uint32_t base  = smem_u32(dsmem);
    const uint32_t xs_hi = base;
    const uint32_t xs_lo = base + GHSB;
    const uint32_t ring  = base + 2 * GHSB;
    const uint32_t mbf   = smem_u32(s_full);
    const uint32_t mbe   = smem_u32(s_empty);
    const int r0 = blockIdx.x * TM;

    if (tid == 0) {
        for (int i = 0; i < URING; i++) {
            MBARRIER_INIT(mbf + i * 8, 1);
            MBARRIER_INIT(mbe + i * 8, 4);
        }
    }
    __syncthreads();

    if (tid == 0) {
#pragma unroll
        for (int s = 0; s < URING; s++) {
            uint32_t sb = ring + s * 2 * WCH;
            MBARRIER_EXPECT_TX(mbf + s * 8, 2 * WCH);
            BULK_G2S(sb,       (const char*)g_WIhi + s * WCH, WCH, mbf + s * 8);
            BULK_G2S(sb + WCH, (const char*)g_WIlo + s * WCH, WCH, mbf + s * 8);
        }
    }

    // ---- load X rows, split fp16 hi/lo ----
    for (int rr = wid; rr < TM; rr += 4) {
        const float* xr = X + (size_t)(r0 + rr) * Dd;
#pragma unroll
        for (int half = 0; half < 2; half++) {
            const int c = half * 128 + 4 * t;
            float4 v = *(const float4*)(xr + c);
            uint32_t h0 = pack_hi(v.x, v.y);
            uint32_t h1 = pack_hi(v.z, v.w);
            uint32_t l0 = pack_lo(v.x, v.y, h0);
            uint32_t l1 = pack_lo(v.z, v.w, h1);
            char* hb = dsmem + (size_t)(rr * HSTR + c) * 2;
            *(uint32_t*)(hb)            = h0;
            *(uint32_t*)(hb + 4)        = h1;
            *(uint32_t*)(hb + GHSB)     = l0;
            *(uint32_t*)(hb + GHSB + 4) = l1;
        }
    }
    __syncthreads();

    const int a_r  = ((t >> 3) & 1) * 8 + (t & 7);
    const int a_k  = ((t >> 4) & 1) * 8;
    const int b_n  = ((t >> 4) & 1) * 8 + (t & 7);
    const int kh   = (t >> 3) & 1;
    const int nbase = wid * 64 + b_n;
    const uint32_t sw16 = ((((uint32_t)nbase >> 2) & 1u) ^ (uint32_t)kh) << 4;

    float D[4][8][4];
#pragma unroll
    for (int i = 0; i < 4; i++)
#pragma unroll
        for (int j = 0; j < 8; j++)
#pragma unroll
            for (int q = 0; q < 4; q++) D[i][j][q] = 0.f;

    for (int g = 0; g < NCH; g++) {
        const int s = g & 1;
        const uint32_t ph = ((uint32_t)g >> 1) & 1u;
        MBARRIER_WAIT_PARITY(mbf + s * 8, ph);

        uint32_t AH[4][4], AL[4][4];
        const int kc = g * 16;
#pragma unroll
        for (int i = 0; i < 4; i++) {
            uint32_t off = (uint32_t)((i * 16 + a_r) * HSTR + kc + a_k) * 2;
            LDSM_X4(AH[i], xs_hi + off);
            LDSM_X4(AL[i], xs_lo + off);
        }
        const uint32_t sb = ring + s * 2 * WCH;
        uint32_t BH[4][4], BL[4][4];
#pragma unroll
        for (int jp = 0; jp < 4; jp++) {
            uint32_t ba = sb + (uint32_t)(nbase + jp * 16) * 32 + sw16;
            LDSM_X4(BH[jp], ba);
            LDSM_X4(BL[jp], ba + WCH);
        }
        __syncwarp();
        if (t == 0) MBARRIER_ARRIVE(mbe + s * 8);

#pragma unroll
        for (int jp = 0; jp < 4; jp++)
#pragma unroll
            for (int i = 0; i < 4; i++) {
                MMAH(D[i][2 * jp],     AH[i], BH[jp][0], BH[jp][1]);
                MMAH(D[i][2 * jp],     AL[i], BH[jp][0], BH[jp][1]);
                MMAH(D[i][2 * jp],     AH[i], BL[jp][0], BL[jp][1]);
                MMAH(D[i][2 * jp + 1], AH[i], BH[jp][2], BH[jp][3]);
                MMAH(D[i][2 * jp + 1], AL[i], BH[jp][2], BH[jp][3]);
                MMAH(D[i][2 * jp + 1], AH[i], BL[jp][2], BL[jp][3]);
            }

        if (tid == 0 && g + URING < NCH) {
            MBARRIER_WAIT_PARITY(mbe + s * 8, ph);
            const int cp = g + URING;
            uint32_t sb2 = ring + s * 2 * WCH;
            MBARRIER_EXPECT_TX(mbf + s * 8, 2 * WCH);
            BULK_G2S(sb2,       (const char*)g_WIhi + cp * WCH, WCH, mbf + s * 8);
            BULK_G2S(sb2 + WCH, (const char*)g_WIlo + cp * WCH, WCH, mbf + s * 8);
        }
    }

    // ---- epilogue: U = D + bias ----
#pragma unroll
    for (int i = 0; i < 4; i++) {
#pragma unroll
        for (int half = 0; half < 2; half++) {
            const int rl = i * 16 + (t >> 2) + half * 8;
            const int gr = r0 + rl;
#pragma unroll
            for (int j = 0; j < 8; j++) {
                const int cc = wid * 64 + j * 8 + 2 * (t & 3);
                float2 b = *(const float2*)(bias + cc);
                *(float2*)(g_U + (size_t)gr * Dd + cc) =
                    make_float2(D[i][j][half * 2] + b.x,
                                D[i][j][half * 2 + 1] + b.y);
            }
        }
    }
}

// ====================== k2: fused HMMA RNN (single fp16 H) ============
__global__ __launch_bounds__(NT, 2) void rnn_kernel(const float* __restrict__ bias,
                                                    float* __restrict__ out) {
    extern __shared__ __align__(128) char dsmem[];
    __shared__ __align__(8) uint64_t s_full[RRING];
    __shared__ __align__(8) uint64_t s_empty[RRING];

    const int tid = threadIdx.x;
    const int wid = tid >> 5;
    const int t   = tid & 31;

    const uint32_t base  = smem_u32(dsmem);
    const uint32_t hs    = base;                     // single H image
    const uint32_t ring  = base + GHSB;              // shared 8-slot ring
    const uint32_t mbf   = smem_u32(s_full);
    const uint32_t mbe   = smem_u32(s_empty);
    const int r0 = blockIdx.x * TM;

    if (tid == 0) {
        for (int i = 0; i < RRING; i++) {
            MBARRIER_INIT(mbf + i * 8, 1);
            MBARRIER_INIT(mbe + i * 8, 4);
        }
    }
    __syncthreads();

    // Prime all 8 slots with chunks 0..7
    if (tid == 0) {
#pragma unroll
        for (int s = 0; s < RRING; s++) {
            MBARRIER_EXPECT_TX(mbf + s * 8, WCH);
            BULK_G2S(ring + s * WCH, (const char*)g_Wf + s * WCH, WCH,
                     mbf + s * 8);
        }
    }

    // ---- step 0: h1 = itau * relu(u_{l-7}) ----
    for (int rr = wid; rr < TM; rr += 4) {
        const int gr = r0 + rr;
        const int l  = gr & (Ll - 1);
        const float* us = (l >= Ks - 1) ? g_U + (size_t)(gr - (Ks - 1)) * Dd
                                        : bias;
#pragma unroll
        for (int half = 0; half < 2; half++) {
            const int c = half * 128 + 4 * t;
            float4 v  = *(const float4*)(us + c);
            float4 it = *(const float4*)(g_itau + c);
            uint32_t p0 = pack_hi(it.x * fmaxf(v.x, 0.f),
                                  it.y * fmaxf(v.y, 0.f));
            uint32_t p1 = pack_hi(it.z * fmaxf(v.z, 0.f),
                                  it.w * fmaxf(v.w, 0.f));
            char* hb = dsmem + (size_t)(rr * HSTR + c) * 2;
            *(uint32_t*)(hb)     = p0;
            *(uint32_t*)(hb + 4) = p1;
        }
    }
    __syncthreads();

    const int a_r  = ((t >> 3) & 1) * 8 + (t & 7);
    const int a_k  = ((t >> 4) & 1) * 8;
    const int b_n  = ((t >> 4) & 1) * 8 + (t & 7);
    const int kh   = (t >> 3) & 1;
    const int nbase = wid * 64 + b_n;
    const uint32_t sw16 = ((((uint32_t)nbase >> 2) & 1u) ^ (uint32_t)kh) << 4;

    int g = 0;
    for (int step = 1; step < Ks; step++) {
        float D[4][8][4];
#pragma unroll
        for (int i = 0; i < 4; i++)
#pragma unroll
            for (int j = 0; j < 8; j++)
#pragma unroll
                for (int q = 0; q < 4; q++) D[i][j][q] = 0.f;

        for (int c = 0; c < NCH; c++, g++) {
            const int s = g & 7;
            const uint32_t ph = ((uint32_t)g >> 3) & 1u;
            MBARRIER_WAIT_PARITY(mbf + s * 8, ph);

            uint32_t AH[4][4];
            const int kc = c * 16;
#pragma unroll
            for (int i = 0; i < 4; i++) {
                uint32_t off = (uint32_t)((i * 16 + a_r) * HSTR + kc + a_k) * 2;
                LDSM_X4(AH[i], hs + off);
            }
            const uint32_t sb = ring + s * WCH;
            uint32_t BH[4][4];
#pragma unroll
            for (int jp = 0; jp < 4; jp++)
                LDSM_X4(BH[jp], sb + (uint32_t)(nbase + jp * 16) * 32 + sw16);
            __syncwarp();
            if (t == 0) MBARRIER_ARRIVE(mbe + s * 8);

#pragma unroll
            for (int jp = 0; jp < 4; jp++)
#pragma unroll
                for (int i = 0; i < 4; i++) {
                    MMAH(D[i][2 * jp],     AH[i], BH[jp][0], BH[jp][1]);
                    MMAH(D[i][2 * jp + 1], AH[i], BH[jp][2], BH[jp][3]);
                }

            // producer (tid 0): refill slot s with chunk g+RRING
            if (tid == 0 && g + RRING < GTOT) {
                MBARRIER_WAIT_PARITY(mbe + s * 8, ph);
                const int cp = (g + RRING) & 15;
                MBARRIER_EXPECT_TX(mbf + s * 8, WCH);
                BULK_G2S(ring + s * WCH, (const char*)g_Wf + cp * WCH, WCH,
                         mbf + s * 8);
            }
        }
        __syncthreads();   // all A-reads of Hs done before epilogue writes

        // ---- fused epilogue: h' = h + itau*(relu(D+u) - h) ----
        const bool last = (step == Ks - 1);
#pragma unroll
        for (int i = 0; i < 4; i++) {
#pragma unroll
            for (int half = 0; half < 2; half++) {
                const int rl = i * 16 + (t >> 2) + half * 8;
                const int gr = r0 + rl;
                const int tt = (gr & (Ll - 1)) - (Ks - 1) + step;
                const float* us = (tt >= 0)
                    ? g_U + (size_t)(gr - (Ks - 1) + step) * Dd : bias;
#pragma unroll
                for (int j = 0; j < 8; j++) {
                    const int cc = wid * 64 + j * 8 + 2 * (t & 3);
                    float2 u  = *(const float2*)(us + cc);
                    float2 it = *(const float2*)(g_itau + cc);
                    const float d0 = D[i][j][half * 2];
                    const float d1 = D[i][j][half * 2 + 1];
                    char* hb = dsmem + (size_t)(rl * HSTR + cc) * 2;
                    uint32_t hv = *(uint32_t*)(hb);
                    __half2 hh = *(__half2*)&hv;
                    float h0 = __half2float(__low2half(hh));
                    float h1 = __half2float(__high2half(hh));
                    float s0 = fmaxf(d0 + u.x, 0.f);
                    float s1 = fmaxf(d1 + u.y, 0.f);
                    float n0 = h0 + it.x * (s0 - h0);
                    float n1 = h1 + it.y * (s1 - h1);
                    if (last) {
                        *(float2*)(out + (size_t)gr * Dd + cc) =
                            make_float2(n0, n1);
                    } else {
                        *(uint32_t*)(hb) = pack_hi(n0, n1);
                    }
                }
            }
        }
        if (!last) __syncthreads();
    }
}

// ---------------------------------------------------------------------------
extern "C" void kernel_launch(void* const* d_in, const int* in_sizes, int n_in,
                              void* d_out, int out_size) {
    (void)in_sizes; (void)n_in; (void)out_size;
    const float* x            = (const float*)d_in[0];
    const float* weight       = (const float*)d_in[1];
    const float* input_weight = (const float*)d_in[2];
    const float* bias         = (const float*)d_in[3];
    const float* tau          = (const float*)d_in[4];
    float* out = (float*)d_out;

    w_prep_kernel<<<Dd * Dd / 256, 256>>>(weight, input_weight, tau);

    cudaFuncSetAttribute(u_gemm_kernel, cudaFuncAttributeMaxDynamicSharedMemorySize,
                         SMEMU);
    u_gemm_kernel<<<ROWS / TM, NT, SMEMU>>>(x, bias);

    cudaFuncSetAttribute(rnn_kernel, cudaFuncAttributeMaxDynamicSharedMemorySize,
                         SMEMR);
    rnn_kernel<<<ROWS / TM, NT, SMEMR>>>(bias, out);
}

// round 8
// speedup vs baseline: 4.7073x; 1.0174x over previous
#include <cuda_runtime.h>
#include <cuda_fp16.h>
#include <cstdint>

// =====================================================================
// LocalRNN: B=8, L=2048, D=256, KSIZE=8   (sm_103 portable HMMA path)
// R8: rnn keeps W fully SMEM-resident (128KB fp16) -> zero streaming,
//     zero producer/ring serialization. TM=128/NT=256, grid 128.
//     w_prep rewritten with SMEM staging -> coalesced 16B stores.
//     u_gemm unchanged from R7. Numerics unchanged (rel_err ~2.3e-4).
// =====================================================================

namespace {
constexpr int Ll = 2048, Dd = 256, Ks = 8, ROWS = 16384;
constexpr int NCH  = 16;               // k-chunks of 16
constexpr int WCH  = 8192;             // packed chunk image: 256n x 32B
constexpr int HSTR = 264;              // H/X row stride in halfs (padded)
// rnn: TM=128, 8 warps, W resident
constexpr int RTM  = 128;
constexpr int RNT  = 256;
constexpr int RHSB = RTM * HSTR * 2;                 // 67584
constexpr int SMEMR = RHSB + NCH * WCH;              // 198656
// u_gemm: TM=64, 4 warps, 2 CTAs/SM, 2-slot (hi+lo) ring
constexpr int UTM  = 64;
constexpr int UNT  = 128;
constexpr int UHSB = UTM * HSTR * 2;                 // 33792
constexpr int URING = 2;
constexpr int SMEMU = 2 * UHSB + URING * 2 * WCH;    // 100352
}

__device__ float g_U[ROWS * Dd];
__device__ __align__(16) __half g_Wf[NCH * 4096];    // 16 x 8192 B
__device__ __align__(16) __half g_WIhi[NCH * 4096];
__device__ __align__(16) __half g_WIlo[NCH * 4096];
__device__ float g_itau[Dd];

// ------------------------- PTX helpers --------------------------------
__device__ __forceinline__ uint32_t smem_u32(const void* p) {
    uint32_t a;
    asm("{ .reg .u64 t; cvta.to.shared.u64 t, %1; cvt.u32.u64 %0, t; }"
        : "=r"(a) : "l"(p));
    return a;
}

#define MBARRIER_INIT(mbar, cnt) \
    asm volatile("mbarrier.init.shared.b64 [%0], %1;" \
                 :: "r"((uint32_t)(mbar)), "r"((uint32_t)(cnt)) : "memory")
#define MBARRIER_ARRIVE(mbar) \
    asm volatile("mbarrier.arrive.shared.b64 _, [%0];" \
                 :: "r"((uint32_t)(mbar)) : "memory")
#define MBARRIER_EXPECT_TX(mbar, bytes) \
    asm volatile("mbarrier.arrive.expect_tx.shared.b64 _, [%0], %1;" \
                 :: "r"((uint32_t)(mbar)), "r"((uint32_t)(bytes)) : "memory")
#define MBARRIER_WAIT_PARITY(mbar, parity) do {                               \
    uint32_t _m = (uint32_t)(mbar);                                           \
    uint32_t _p = (uint32_t)(parity);                                         \
    uint32_t _done;                                                           \
    asm volatile(                                                             \
        "{\n\t.reg .pred p;\n\t"                                              \
        "mbarrier.try_wait.parity.acquire.cta.shared::cta.b64 p, [%1], %2;\n\t" \
        "selp.b32 %0, 1, 0, p;\n\t}"                                          \
        : "=r"(_done) : "r"(_m), "r"(_p) : "memory");                         \
    if (!_done) {                                                             \
        asm volatile(                                                         \
            "{\n\t.reg .pred P1;\n\t"                                         \
            "WL_%=:\n\t"                                                      \
            "mbarrier.try_wait.parity.acquire.cta.shared::cta.b64 P1, [%0], %1, 0x989680;\n\t" \
            "@P1 bra.uni WD_%=;\n\t"                                          \
            "bra.uni WL_%=;\n\t"                                              \
            "WD_%=:\n\t}"                                                     \
            :: "r"(_m), "r"(_p) : "memory");                                  \
    }                                                                         \
} while (0)

#define BULK_G2S(dst, src, bytes, mbar)                                       \
    asm volatile(                                                             \
        "cp.async.bulk.shared::cluster.global.mbarrier::complete_tx::bytes "  \
        "[%0], [%1], %2, [%3];"                                               \
        :: "r"((uint32_t)(dst)), "l"(src), "r"((uint32_t)(bytes)),            \
           "r"((uint32_t)(mbar)) : "memory")

#define LDSM_X4(r, addr)                                                      \
    asm volatile("ldmatrix.sync.aligned.m8n8.x4.shared.b16 "                  \
                 "{%0,%1,%2,%3}, [%4];"                                       \
                 : "=r"((r)[0]), "=r"((r)[1]), "=r"((r)[2]), "=r"((r)[3])     \
                 : "r"(addr))

#define MMAH(d, a, b0_, b1_)                                                  \
    asm volatile(                                                             \
        "mma.sync.aligned.m16n8k16.row.col.f32.f16.f16.f32 "                  \
        "{%0,%1,%2,%3},{%4,%5,%6,%7},{%8,%9},{%0,%1,%2,%3};"                  \
        : "+f"((d)[0]), "+f"((d)[1]), "+f"((d)[2]), "+f"((d)[3])              \
        : "r"((a)[0]), "r"((a)[1]), "r"((a)[2]), "r"((a)[3]),                 \
          "r"(b0_), "r"(b1_))

__device__ __forceinline__ uint32_t pack_hi(float x, float y) {
    __half2 p = __floats2half2_rn(x, y);
    return *(uint32_t*)&p;
}
__device__ __forceinline__ uint32_t pack_lo(float x, float y, uint32_t hi) {
    __half2 h = *(__half2*)&hi;
    __half2 p = __floats2half2_rn(x - __half2float(__low2half(h)),
                                  y - __half2float(__high2half(h)));
    return *(uint32_t*)&p;
}

// ====================== k0: W prep (SMEM-staged, coalesced) ===========
// Layout: off(k,n) = (k>>4)*8192 + n*32 + (((k>>3&1)^(n>>2&1))<<4) + (k&7)*2
// One block per chunk (16 k-rows). Pass 0: W -> g_Wf. Pass 1: Win -> hi/lo.
__global__ __launch_bounds__(256) void w_prep_kernel(const float* __restrict__ W,
                                                     const float* __restrict__ Win,
                                                     const float* __restrict__ tau) {
    __shared__ float tile[16][256];
    const int c   = blockIdx.x;          // chunk 0..15
    const int tid = threadIdx.x;         // = n
    if (c == 0 && tid < Dd) g_itau[tid] = 1.0f / tau[tid];

    for (int pass = 0; pass < 2; pass++) {
        const float* src = pass ? Win : W;
        __syncthreads();
#pragma unroll
        for (int kk = 0; kk < 16; kk++)
            tile[kk][tid] = src[(size_t)(c * 16 + kk) * Dd + tid];
        __syncthreads();

        const uint32_t nsw = ((uint32_t)(tid >> 2) & 1u);
#pragma unroll
        for (int kh = 0; kh < 2; kh++) {
            uint32_t off = (uint32_t)c * 8192u + (uint32_t)tid * 32u +
                           (((uint32_t)kh ^ nsw) << 4);
            __half h8[8], l8[8];
#pragma unroll
            for (int j = 0; j < 8; j++) {
                float v = tile[kh * 8 + j][tid];
                __half hi = __float2half_rn(v);
                h8[j] = hi;
                l8[j] = __float2half_rn(v - __half2float(hi));
            }
            if (pass == 0) {
                *(uint4*)((char*)g_Wf + off) = *(uint4*)h8;
            } else {
                *(uint4*)((char*)g_WIhi + off) = *(uint4*)h8;
                *(uint4*)((char*)g_WIlo + off) = *(uint4*)l8;
            }
        }
    }
}

// ====================== k1: U = X @ Win + bias (HMMA, 3-term) =========
__global__ __launch_bounds__(UNT, 2) void u_gemm_kernel(const float* __restrict__ X,
                                                        const float* __restrict__ bias) {
    extern __shared__ __align__(128) char dsmem[];
    __shared__ __align__(8) uint64_t s_full[URING];
    __shared__ __align__(8) uint64_t s_empty[URING];

    const int tid = threadIdx.x;
    const int wid = tid >> 5;
    const int t   = tid & 31;

    const uint32_t base  = smem_u32(dsmem);
    const uint32_t xs_hi = base;
    const uint32_t xs_lo = base + UHSB;
    const uint32_t ring  = base + 2 * UHSB;
    const uint32_t mbf   = smem_u32(s_full);
    const uint32_t mbe   = smem_u32(s_empty);
    const int r0 = blockIdx.x * UTM;

    if (tid == 0) {
        for (int i = 0; i < URING; i++) {
            MBARRIER_INIT(mbf + i * 8, 1);
            MBARRIER_INIT(mbe + i * 8, 4);
        }
    }
    __syncthreads();

    if (tid == 0) {
#pragma unroll
        for (int s = 0; s < URING; s++) {
            uint32_t sb = ring + s * 2 * WCH;
            MBARRIER_EXPECT_TX(mbf + s * 8, 2 * WCH);
            BULK_G2S(sb,       (const char*)g_WIhi + s * WCH, WCH, mbf + s * 8);
            BULK_G2S(sb + WCH, (const char*)g_WIlo + s * WCH, WCH, mbf + s * 8);
        }
    }

    // ---- load X rows, split fp16 hi/lo ----
    for (int rr = wid; rr < UTM; rr += 4) {
        const float* xr = X + (size_t)(r0 + rr) * Dd;
#pragma unroll
        for (int half = 0; half < 2; half++) {
            const int c = half * 128 + 4 * t;
            float4 v = *(const float4*)(xr + c);
            uint32_t h0 = pack_hi(v.x, v.y);
            uint32_t h1 = pack_hi(v.z, v.w);
            uint32_t l0 = pack_lo(v.x, v.y, h0);
            uint32_t l1 = pack_lo(v.z, v.w, h1);
            char* hb = dsmem + (size_t)(rr * HSTR + c) * 2;
            *(uint32_t*)(hb)            = h0;
            *(uint32_t*)(hb + 4)        = h1;
            *(uint32_t*)(hb + UHSB)     = l0;
            *(uint32_t*)(hb + UHSB + 4) = l1;
        }
    }
    __syncthreads();

    const int a_r  = ((t >> 3) & 1) * 8 + (t & 7);
    const int a_k  = ((t >> 4) & 1) * 8;
    const int b_n  = ((t >> 4) & 1) * 8 + (t & 7);
    const int kh   = (t >> 3) & 1;
    const int nbase = wid * 64 + b_n;
    const uint32_t sw16 = ((((uint32_t)nbase >> 2) & 1u) ^ (uint32_t)kh) << 4;

    float D[4][8][4];
#pragma unroll
    for (int i = 0; i < 4; i++)
#pragma unroll
        for (int j = 0; j < 8; j++)
#pragma unroll
            for (int q = 0; q < 4; q++) D[i][j][q] = 0.f;

    for (int g = 0; g < NCH; g++) {
        const int s = g & 1;
        const uint32_t ph = ((uint32_t)g >> 1) & 1u;
        MBARRIER_WAIT_PARITY(mbf + s * 8, ph);

        uint32_t AH[4][4], AL[4][4];
        const int kc = g * 16;
#pragma unroll
        for (int i = 0; i < 4; i++) {
            uint32_t off = (uint32_t)((i * 16 + a_r) * HSTR + kc + a_k) * 2;
            LDSM_X4(AH[i], xs_hi + off);
            LDSM_X4(AL[i], xs_lo + off);
        }
        const uint32_t sb = ring + s * 2 * WCH;
        uint32_t BH[4][4], BL[4][4];
#pragma unroll
        for (int jp = 0; jp < 4; jp++) {
            uint32_t ba = sb + (uint32_t)(nbase + jp * 16) * 32 + sw16;
            LDSM_X4(BH[jp], ba);
            LDSM_X4(BL[jp], ba + WCH);
        }
        __syncwarp();
        if (t == 0) MBARRIER_ARRIVE(mbe + s * 8);

#pragma unroll
        for (int jp = 0; jp < 4; jp++)
#pragma unroll
            for (int i = 0; i < 4; i++) {
                MMAH(D[i][2 * jp],     AH[i], BH[jp][0], BH[jp][1]);
                MMAH(D[i][2 * jp],     AL[i], BH[jp][0], BH[jp][1]);
                MMAH(D[i][2 * jp],     AH[i], BL[jp][0], BL[jp][1]);
                MMAH(D[i][2 * jp + 1], AH[i], BH[jp][2], BH[jp][3]);
                MMAH(D[i][2 * jp + 1], AL[i], BH[jp][2], BH[jp][3]);
                MMAH(D[i][2 * jp + 1], AH[i], BL[jp][2], BL[jp][3]);
            }

        if (tid == 0 && g + URING < NCH) {
            MBARRIER_WAIT_PARITY(mbe + s * 8, ph);
            const int cp = g + URING;
            uint32_t sb2 = ring + s * 2 * WCH;
            MBARRIER_EXPECT_TX(mbf + s * 8, 2 * WCH);
            BULK_G2S(sb2,       (const char*)g_WIhi + cp * WCH, WCH, mbf + s * 8);
            BULK_G2S(sb2 + WCH, (const char*)g_WIlo + cp * WCH, WCH, mbf + s * 8);
        }
    }

    // ---- epilogue: U = D + bias ----
#pragma unroll
    for (int i = 0; i < 4; i++) {
#pragma unroll
        for (int half = 0; half < 2; half++) {
            const int rl = i * 16 + (t >> 2) + half * 8;
            const int gr = r0 + rl;
#pragma unroll
            for (int j = 0; j < 8; j++) {
                const int cc = wid * 64 + j * 8 + 2 * (t & 3);
                float2 b = *(const float2*)(bias + cc);
                *(float2*)(g_U + (size_t)gr * Dd + cc) =
                    make_float2(D[i][j][half * 2] + b.x,
                                D[i][j][half * 2 + 1] + b.y);
            }
        }
    }
}

// ====================== k2: fused HMMA RNN (W resident) ===============
__global__ __launch_bounds__(RNT, 1) void rnn_kernel(const float* __restrict__ bias,
                                                     float* __restrict__ out) {
    extern __shared__ __align__(128) char dsmem[];
    __shared__ __align__(8) uint64_t s_full[1];

    const int tid = threadIdx.x;
    const int wid = tid >> 5;
    const int t   = tid & 31;
    const int mi  = wid >> 2;   // 0/1  -> rows mi*64
    const int nj  = wid & 3;    // 0..3 -> cols nj*64

    const uint32_t hs  = smem_u32(dsmem);            // H image, 67584 B
    const uint32_t ws  = hs + RHSB;                  // W resident, 131072 B
    const uint32_t mbf = smem_u32(s_full);
    const int r0 = blockIdx.x * RTM;

    if (tid == 0) {
        MBARRIER_INIT(mbf, 1);
        MBARRIER_EXPECT_TX(mbf, NCH * WCH);
#pragma unroll
        for (int s = 0; s < NCH; s++)
            BULK_G2S(ws + s * WCH, (const char*)g_Wf + s * WCH, WCH, mbf);
    }

    // ---- step 0: h1 = itau * relu(u_{l-7}) ----
    for (int rr = wid; rr < RTM; rr += 8) {
        const int gr = r0 + rr;
        const int l  = gr & (Ll - 1);
        const float* us = (l >= Ks - 1) ? g_U + (size_t)(gr - (Ks - 1)) * Dd
                                        : bias;
#pragma unroll
        for (int half = 0; half < 2; half++) {
            const int c = half * 128 + 4 * t;
            float4 v  = *(const float4*)(us + c);
            float4 it = *(const float4*)(g_itau + c);
            uint32_t p0 = pack_hi(it.x * fmaxf(v.x, 0.f),
                                  it.y * fmaxf(v.y, 0.f));
            uint32_t p1 = pack_hi(it.z * fmaxf(v.z, 0.f),
                                  it.w * fmaxf(v.w, 0.f));
            char* hb = dsmem + (size_t)(rr * HSTR + c) * 2;
            *(uint32_t*)(hb)     = p0;
            *(uint32_t*)(hb + 4) = p1;
        }
    }
    __syncthreads();
    MBARRIER_WAIT_PARITY(mbf, 0);   // W resident from here on

    const int a_r  = ((t >> 3) & 1) * 8 + (t & 7);
    const int a_k  = ((t >> 4) & 1) * 8;
    const int b_n  = ((t >> 4) & 1) * 8 + (t & 7);
    const int kh   = (t >> 3) & 1;
    const int nbase = nj * 64 + b_n;
    const uint32_t sw16 = ((((uint32_t)nbase >> 2) & 1u) ^ (uint32_t)kh) << 4;

    for (int step = 1; step < Ks; step++) {
        float D[4][8][4];
#pragma unroll
        for (int i = 0; i < 4; i++)
#pragma unroll
            for (int j = 0; j < 8; j++)
#pragma unroll
                for (int q = 0; q < 4; q++) D[i][j][q] = 0.f;

#pragma unroll 4
        for (int c = 0; c < NCH; c++) {
            uint32_t AH[4][4];
            const int kc = c * 16;
#pragma unroll
            for (int i = 0; i < 4; i++) {
                uint32_t off =
                    (uint32_t)((mi * 64 + i * 16 + a_r) * HSTR + kc + a_k) * 2;
                LDSM_X4(AH[i], hs + off);
            }
            const uint32_t sb = ws + c * WCH;
            uint32_t BH[4][4];
#pragma unroll
            for (int jp = 0; jp < 4; jp++)
                LDSM_X4(BH[jp], sb + (uint32_t)(nbase + jp * 16) * 32 + sw16);

#pragma unroll
            for (int jp = 0; jp < 4; jp++)
#pragma unroll
                for (int i = 0; i < 4; i++) {
                    MMAH(D[i][2 * jp],     AH[i], BH[jp][0], BH[jp][1]);
                    MMAH(D[i][2 * jp + 1], AH[i], BH[jp][2], BH[jp][3]);
                }
        }
        __syncthreads();   // all A-reads of Hs done before epilogue writes

        // ---- fused epilogue: h' = h + itau*(relu(D+u) - h) ----
        const bool last = (step == Ks - 1);
#pragma unroll
        for (int i = 0; i < 4; i++) {
#pragma unroll
            for (int half = 0; half < 2; half++) {
                const int rl = mi * 64 + i * 16 + (t >> 2) + half * 8;
                const int gr = r0 + rl;
                const int tt = (gr & (Ll - 1)) - (Ks - 1) + step;
                const float* us = (tt >= 0)
                    ? g_U + (size_t)(gr - (Ks - 1) + step) * Dd : bias;
#pragma unroll
                for (int j = 0; j < 8; j++) {
                    const int cc = nj * 64 + j * 8 + 2 * (t & 3);
                    float2 u  = *(const float2*)(us + cc);
                    float2 it = *(const float2*)(g_itau + cc);
                    const float d0 = D[i][j][half * 2];
                    const float d1 = D[i][j][half * 2 + 1];
                    char* hb = dsmem + (size_t)(rl * HSTR + cc) * 2;
                    uint32_t hv = *(uint32_t*)(hb);
                    __half2 hh = *(__half2*)&hv;
                    float h0 = __half2float(__low2half(hh));
                    float h1 = __half2float(__high2half(hh));
                    float s0 = fmaxf(d0 + u.x, 0.f);
                    float s1 = fmaxf(d1 + u.y, 0.f);
                    float n0 = h0 + it.x * (s0 - h0);
                    float n1 = h1 + it.y * (s1 - h1);
                    if (last) {
                        *(float2*)(out + (size_t)gr * Dd + cc) =
                            make_float2(n0, n1);
                    } else {
                        *(uint32_t*)(hb) = pack_hi(n0, n1);
                    }
                }
            }
        }
        if (!last) __syncthreads();
    }
}

// ---------------------------------------------------------------------------
extern "C" void kernel_launch(void* const* d_in, const int* in_sizes, int n_in,
                              void* d_out, int out_size) {
    (void)in_sizes; (void)n_in; (void)out_size;
    const float* x            = (const float*)d_in[0];
    const float* weight       = (const float*)d_in[1];
    const float* input_weight = (const float*)d_in[2];
    const float* bias         = (const float*)d_in[3];
    const float* tau          = (const float*)d_in[4];
    float* out = (float*)d_out;

    w_prep_kernel<<<NCH, 256>>>(weight, input_weight, tau);

    cudaFuncSetAttribute(u_gemm_kernel, cudaFuncAttributeMaxDynamicSharedMemorySize,
                         SMEMU);
    u_gemm_kernel<<<ROWS / UTM, UNT, SMEMU>>>(x, bias);

    cudaFuncSetAttribute(rnn_kernel, cudaFuncAttributeMaxDynamicSharedMemorySize,
                         SMEMR);
    rnn_kernel<<<ROWS / RTM, RNT, SMEMR>>>(bias, out);
}

// round 9
// speedup vs baseline: 5.1905x; 1.1026x over previous
#include <cuda_runtime.h>
#include <cuda_fp16.h>
#include <cstdint>

// =====================================================================
// LocalRNN: B=8, L=2048, D=256, KSIZE=8   (sm_103 portable HMMA path)
// R9: rnn at legacy-HMMA rate ceiling (rt~16cyc/SMSP) -> untouched (R8).
//     u_gemm cut to single-term fp16 (X and Win both single fp16):
//     error budget calibrated from measured 2.27e-4 -> predicted ~3e-4.
//     w_prep: 32 blocks, single pass per (chunk, matrix).
// =====================================================================

namespace {
constexpr int Ll = 2048, Dd = 256, Ks = 8, ROWS = 16384;
constexpr int NCH  = 16;               // k-chunks of 16
constexpr int WCH  = 8192;             // packed chunk image: 256n x 32B
constexpr int HSTR = 264;              // H/X row stride in halfs (padded)
// rnn: TM=128, 8 warps, W resident (R8, unchanged)
constexpr int RTM  = 128;
constexpr int RNT  = 256;
constexpr int RHSB = RTM * HSTR * 2;                 // 67584
constexpr int SMEMR = RHSB + NCH * WCH;              // 198656
// u_gemm: TM=64, 4 warps, single-fp16, 4-slot Win ring
constexpr int UTM  = 64;
constexpr int UNT  = 128;
constexpr int UHSB = UTM * HSTR * 2;                 // 33792
constexpr int URING = 4;
constexpr int SMEMU = UHSB + URING * WCH;            // 66560 (2+ CTAs/SM)
}

__device__ float g_U[ROWS * Dd];
__device__ __align__(16) __half g_Wf[NCH * 4096];    // 16 x 8192 B
__device__ __align__(16) __half g_WIf[NCH * 4096];   // Win single fp16
__device__ float g_itau[Dd];

// ------------------------- PTX helpers --------------------------------
__device__ __forceinline__ uint32_t smem_u32(const void* p) {
    uint32_t a;
    asm("{ .reg .u64 t; cvta.to.shared.u64 t, %1; cvt.u32.u64 %0, t; }"
        : "=r"(a) : "l"(p));
    return a;
}

#define MBARRIER_INIT(mbar, cnt) \
    asm volatile("mbarrier.init.shared.b64 [%0], %1;" \
                 :: "r"((uint32_t)(mbar)), "r"((uint32_t)(cnt)) : "memory")
#define MBARRIER_ARRIVE(mbar) \
    asm volatile("mbarrier.arrive.shared.b64 _, [%0];" \
                 :: "r"((uint32_t)(mbar)) : "memory")
#define MBARRIER_EXPECT_TX(mbar, bytes) \
    asm volatile("mbarrier.arrive.expect_tx.shared.b64 _, [%0], %1;" \
                 :: "r"((uint32_t)(mbar)), "r"((uint32_t)(bytes)) : "memory")
#define MBARRIER_WAIT_PARITY(mbar, parity) do {                               \
    uint32_t _m = (uint32_t)(mbar);                                           \
    uint32_t _p = (uint32_t)(parity);                                         \
    uint32_t _done;                                                           \
    asm volatile(                                                             \
        "{\n\t.reg .pred p;\n\t"                                              \
        "mbarrier.try_wait.parity.acquire.cta.shared::cta.b64 p, [%1], %2;\n\t" \
        "selp.b32 %0, 1, 0, p;\n\t}"                                          \
        : "=r"(_done) : "r"(_m), "r"(_p) : "memory");                         \
    if (!_done) {                                                             \
        asm volatile(                                                         \
            "{\n\t.reg .pred P1;\n\t"                                         \
            "WL_%=:\n\t"                                                      \
            "mbarrier.try_wait.parity.acquire.cta.shared::cta.b64 P1, [%0], %1, 0x989680;\n\t" \
            "@P1 bra.uni WD_%=;\n\t"                                          \
            "bra.uni WL_%=;\n\t"                                              \
            "WD_%=:\n\t}"                                                     \
            :: "r"(_m), "r"(_p) : "memory");                                  \
    }                                                                         \
} while (0)

#define BULK_G2S(dst, src, bytes, mbar)                                       \
    asm volatile(                                                             \
        "cp.async.bulk.shared::cluster.global.mbarrier::complete_tx::bytes "  \
        "[%0], [%1], %2, [%3];"                                               \
        :: "r"((uint32_t)(dst)), "l"(src), "r"((uint32_t)(bytes)),            \
           "r"((uint32_t)(mbar)) : "memory")

#define LDSM_X4(r, addr)                                                      \
    asm volatile("ldmatrix.sync.aligned.m8n8.x4.shared.b16 "                  \
                 "{%0,%1,%2,%3}, [%4];"                                       \
                 : "=r"((r)[0]), "=r"((r)[1]), "=r"((r)[2]), "=r"((r)[3])     \
                 : "r"(addr))

#define MMAH(d, a, b0_, b1_)                                                  \
    asm volatile(                                                             \
        "mma.sync.aligned.m16n8k16.row.col.f32.f16.f16.f32 "                  \
        "{%0,%1,%2,%3},{%4,%5,%6,%7},{%8,%9},{%0,%1,%2,%3};"                  \
        : "+f"((d)[0]), "+f"((d)[1]), "+f"((d)[2]), "+f"((d)[3])              \
        : "r"((a)[0]), "r"((a)[1]), "r"((a)[2]), "r"((a)[3]),                 \
          "r"(b0_), "r"(b1_))

__device__ __forceinline__ uint32_t pack_hi(float x, float y) {
    __half2 p = __floats2half2_rn(x, y);
    return *(uint32_t*)&p;
}

// ====================== k0: W prep (32 blocks, coalesced) =============
// Layout: off(k,n) = (k>>4)*8192 + n*32 + (((k>>3&1)^(n>>2&1))<<4) + (k&7)*2
// Block b: chunk = b>>1, matrix = b&1 (0: W -> g_Wf, 1: Win -> g_WIf).
__global__ __launch_bounds__(256) void w_prep_kernel(const float* __restrict__ W,
                                                     const float* __restrict__ Win,
                                                     const float* __restrict__ tau) {
    __shared__ float tile[16][256];
    const int c   = blockIdx.x >> 1;
    const int m   = blockIdx.x & 1;
    const int tid = threadIdx.x;         // = n
    const float* src = m ? Win : W;
    __half* dst = m ? g_WIf : g_Wf;
    if (blockIdx.x == 0 && tid < Dd) g_itau[tid] = 1.0f / tau[tid];

#pragma unroll
    for (int kk = 0; kk < 16; kk++)
        tile[kk][tid] = src[(size_t)(c * 16 + kk) * Dd + tid];
    __syncthreads();

    const uint32_t nsw = ((uint32_t)(tid >> 2) & 1u);
#pragma unroll
    for (int kh = 0; kh < 2; kh++) {
        uint32_t off = (uint32_t)c * 8192u + (uint32_t)tid * 32u +
                       (((uint32_t)kh ^ nsw) << 4);
        __half h8[8];
#pragma unroll
        for (int j = 0; j < 8; j++)
            h8[j] = __float2half_rn(tile[kh * 8 + j][tid]);
        *(uint4*)((char*)dst + off) = *(uint4*)h8;
    }
}

// ====================== k1: U = X @ Win + bias (1-term fp16) ==========
__global__ __launch_bounds__(UNT, 2) void u_gemm_kernel(const float* __restrict__ X,
                                                        const float* __restrict__ bias) {
    extern __shared__ __align__(128) char dsmem[];
    __shared__ __align__(8) uint64_t s_full[URING];
    __shared__ __align__(8) uint64_t s_empty[URING];

    const int tid = threadIdx.x;
    const int wid = tid >> 5;
    const int t   = tid & 31;

    const uint32_t base = smem_u32(dsmem);
    const uint32_t xs   = base;                      // single X image
    const uint32_t ring = base + UHSB;               // 4 x WCH
    const uint32_t mbf  = smem_u32(s_full);
    const uint32_t mbe  = smem_u32(s_empty);
    const int r0 = blockIdx.x * UTM;

    if (tid == 0) {
        for (int i = 0; i < URING; i++) {
            MBARRIER_INIT(mbf + i * 8, 1);
            MBARRIER_INIT(mbe + i * 8, 4);
        }
    }
    __syncthreads();

    if (tid == 0) {
#pragma unroll
        for (int s = 0; s < URING; s++) {
            MBARRIER_EXPECT_TX(mbf + s * 8, WCH);
            BULK_G2S(ring + s * WCH, (const char*)g_WIf + s * WCH, WCH,
                     mbf + s * 8);
        }
    }

    // ---- load X rows, convert to single fp16 ----
    for (int rr = wid; rr < UTM; rr += 4) {
        const float* xr = X + (size_t)(r0 + rr) * Dd;
#pragma unroll
        for (int half = 0; half < 2; half++) {
            const int c = half * 128 + 4 * t;
            float4 v = *(const float4*)(xr + c);
            char* hb = dsmem + (size_t)(rr * HSTR + c) * 2;
            *(uint32_t*)(hb)     = pack_hi(v.x, v.y);
            *(uint32_t*)(hb + 4) = pack_hi(v.z, v.w);
        }
    }
    __syncthreads();

    const int a_r  = ((t >> 3) & 1) * 8 + (t & 7);
    const int a_k  = ((t >> 4) & 1) * 8;
    const int b_n  = ((t >> 4) & 1) * 8 + (t & 7);
    const int kh   = (t >> 3) & 1;
    const int nbase = wid * 64 + b_n;
    const uint32_t sw16 = ((((uint32_t)nbase >> 2) & 1u) ^ (uint32_t)kh) << 4;

    float D[4][8][4];
#pragma unroll
    for (int i = 0; i < 4; i++)
#pragma unroll
        for (int j = 0; j < 8; j++)
#pragma unroll
            for (int q = 0; q < 4; q++) D[i][j][q] = 0.f;

    for (int g = 0; g < NCH; g++) {
        const int s = g & 3;
        const uint32_t ph = ((uint32_t)g >> 2) & 1u;
        MBARRIER_WAIT_PARITY(mbf + s * 8, ph);

        uint32_t AH[4][4];
        const int kc = g * 16;
#pragma unroll
        for (int i = 0; i < 4; i++) {
            uint32_t off = (uint32_t)((i * 16 + a_r) * HSTR + kc + a_k) * 2;
            LDSM_X4(AH[i], xs + off);
        }
        const uint32_t sb = ring + s * WCH;
        uint32_t BH[4][4];
#pragma unroll
        for (int jp = 0; jp < 4; jp++)
            LDSM_X4(BH[jp], sb + (uint32_t)(nbase + jp * 16) * 32 + sw16);
        __syncwarp();
        if (t == 0) MBARRIER_ARRIVE(mbe + s * 8);

#pragma unroll
        for (int jp = 0; jp < 4; jp++)
#pragma unroll
            for (int i = 0; i < 4; i++) {
                MMAH(D[i][2 * jp],     AH[i], BH[jp][0], BH[jp][1]);
                MMAH(D[i][2 * jp + 1], AH[i], BH[jp][2], BH[jp][3]);
            }

        if (tid == 0 && g + URING < NCH) {
            MBARRIER_WAIT_PARITY(mbe + s * 8, ph);
            const int cp = g + URING;
            MBARRIER_EXPECT_TX(mbf + s * 8, WCH);
            BULK_G2S(ring + s * WCH, (const char*)g_WIf + cp * WCH, WCH,
                     mbf + s * 8);
        }
    }

    // ---- epilogue: U = D + bias ----
#pragma unroll
    for (int i = 0; i < 4; i++) {
#pragma unroll
        for (int half = 0; half < 2; half++) {
            const int rl = i * 16 + (t >> 2) + half * 8;
            const int gr = r0 + rl;
#pragma unroll
            for (int j = 0; j < 8; j++) {
                const int cc = wid * 64 + j * 8 + 2 * (t & 3);
                float2 b = *(const float2*)(bias + cc);
                *(float2*)(g_U + (size_t)gr * Dd + cc) =
                    make_float2(D[i][j][half * 2] + b.x,
                                D[i][j][half * 2 + 1] + b.y);
            }
        }
    }
}

// ====================== k2: fused HMMA RNN (W resident, R8) ===========
__global__ __launch_bounds__(RNT, 1) void rnn_kernel(const float* __restrict__ bias,
                                                     float* __restrict__ out) {
    extern __shared__ __align__(128) char dsmem[];
    __shared__ __align__(8) uint64_t s_full[1];

    const int tid = threadIdx.x;
    const int wid = tid >> 5;
    const int t   = tid & 31;
    const int mi  = wid >> 2;
    const int nj  = wid & 3;

    const uint32_t hs  = smem_u32(dsmem);
    const uint32_t ws  = hs + RHSB;
    const uint32_t mbf = smem_u32(s_full);
    const int r0 = blockIdx.x * RTM;

    if (tid == 0) {
        MBARRIER_INIT(mbf, 1);
        MBARRIER_EXPECT_TX(mbf, NCH * WCH);
#pragma unroll
        for (int s = 0; s < NCH; s++)
            BULK_G2S(ws + s * WCH, (const char*)g_Wf + s * WCH, WCH, mbf);
    }

    // ---- step 0: h1 = itau * relu(u_{l-7}) ----
    for (int rr = wid; rr < RTM; rr += 8) {
        const int gr = r0 + rr;
        const int l  = gr & (Ll - 1);
        const float* us = (l >= Ks - 1) ? g_U + (size_t)(gr - (Ks - 1)) * Dd
                                        : bias;
#pragma unroll
        for (int half = 0; half < 2; half++) {
            const int c = half * 128 + 4 * t;
            float4 v  = *(const float4*)(us + c);
            float4 it = *(const float4*)(g_itau + c);
            uint32_t p0 = pack_hi(it.x * fmaxf(v.x, 0.f),
                                  it.y * fmaxf(v.y, 0.f));
            uint32_t p1 = pack_hi(it.z * fmaxf(v.z, 0.f),
                                  it.w * fmaxf(v.w, 0.f));
            char* hb = dsmem + (size_t)(rr * HSTR + c) * 2;
            *(uint32_t*)(hb)     = p0;
            *(uint32_t*)(hb + 4) = p1;
        }
    }
    __syncthreads();
    MBARRIER_WAIT_PARITY(mbf, 0);

    const int a_r  = ((t >> 3) & 1) * 8 + (t & 7);
    const int a_k  = ((t >> 4) & 1) * 8;
    const int b_n  = ((t >> 4) & 1) * 8 + (t & 7);
    const int kh   = (t >> 3) & 1;
    const int nbase = nj * 64 + b_n;
    const uint32_t sw16 = ((((uint32_t)nbase >> 2) & 1u) ^ (uint32_t)kh) << 4;

    for (int step = 1; step < Ks; step++) {
        float D[4][8][4];
#pragma unroll
        for (int i = 0; i < 4; i++)
#pragma unroll
            for (int j = 0; j < 8; j++)
#pragma unroll
                for (int q = 0; q < 4; q++) D[i][j][q] = 0.f;

#pragma unroll 4
        for (int c = 0; c < NCH; c++) {
            uint32_t AH[4][4];
            const int kc = c * 16;
#pragma unroll
            for (int i = 0; i < 4; i++) {
                uint32_t off =
                    (uint32_t)((mi * 64 + i * 16 + a_r) * HSTR + kc + a_k) * 2;
                LDSM_X4(AH[i], hs + off);
            }
            const uint32_t sb = ws + c * WCH;
            uint32_t BH[4][4];
#pragma unroll
            for (int jp = 0; jp < 4; jp++)
                LDSM_X4(BH[jp], sb + (uint32_t)(nbase + jp * 16) * 32 + sw16);

#pragma unroll
            for (int jp = 0; jp < 4; jp++)
#pragma unroll
                for (int i = 0; i < 4; i++) {
                    MMAH(D[i][2 * jp],     AH[i], BH[jp][0], BH[jp][1]);
                    MMAH(D[i][2 * jp + 1], AH[i], BH[jp][2], BH[jp][3]);
                }
        }
        __syncthreads();

        const bool last = (step == Ks - 1);
#pragma unroll
        for (int i = 0; i < 4; i++) {
#pragma unroll
            for (int half = 0; half < 2; half++) {
                const int rl = mi * 64 + i * 16 + (t >> 2) + half * 8;
                const int gr = r0 + rl;
                const int tt = (gr & (Ll - 1)) - (Ks - 1) + step;
                const float* us = (tt >= 0)
                    ? g_U + (size_t)(gr - (Ks - 1) + step) * Dd : bias;
#pragma unroll
                for (int j = 0; j < 8; j++) {
                    const int cc = nj * 64 + j * 8 + 2 * (t & 3);
                    float2 u  = *(const float2*)(us + cc);
                    float2 it = *(const float2*)(g_itau + cc);
                    const float d0 = D[i][j][half * 2];
                    const float d1 = D[i][j][half * 2 + 1];
                    char* hb = dsmem + (size_t)(rl * HSTR + cc) * 2;
                    uint32_t hv = *(uint32_t*)(hb);
                    __half2 hh = *(__half2*)&hv;
                    float h0 = __half2float(__low2half(hh));
                    float h1 = __half2float(__high2half(hh));
                    float s0 = fmaxf(d0 + u.x, 0.f);
                    float s1 = fmaxf(d1 + u.y, 0.f);
                    float n0 = h0 + it.x * (s0 - h0);
                    float n1 = h1 + it.y * (s1 - h1);
                    if (last) {
                        *(float2*)(out + (size_t)gr * Dd + cc) =
                            make_float2(n0, n1);
                    } else {
                        *(uint32_t*)(hb) = pack_hi(n0, n1);
                    }
                }
            }
        }
        if (!last) __syncthreads();
    }
}

// ---------------------------------------------------------------------------
extern "C" void kernel_launch(void* const* d_in, const int* in_sizes, int n_in,
                              void* d_out, int out_size) {
    (void)in_sizes; (void)n_in; (void)out_size;
    const float* x            = (const float*)d_in[0];
    const float* weight       = (const float*)d_in[1];
    const float* input_weight = (const float*)d_in[2];
    const float* bias         = (const float*)d_in[3];
    const float* tau          = (const float*)d_in[4];
    float* out = (float*)d_out;

    w_prep_kernel<<<2 * NCH, 256>>>(weight, input_weight, tau);

    cudaFuncSetAttribute(u_gemm_kernel, cudaFuncAttributeMaxDynamicSharedMemorySize,
                         SMEMU);
    u_gemm_kernel<<<ROWS / UTM, UNT, SMEMU>>>(x, bias);

    cudaFuncSetAttribute(rnn_kernel, cudaFuncAttributeMaxDynamicSharedMemorySize,
                         SMEMR);
    rnn_kernel<<<ROWS / RTM, RNT, SMEMR>>>(bias, out);
}

// round 10
// speedup vs baseline: 6.2254x; 1.1994x over previous
#include <cuda_runtime.h>
#include <cuda_fp16.h>
#include <cstdint>

// =====================================================================
// LocalRNN: B=8, L=2048, D=256, KSIZE=8   (sm_103 portable HMMA path)
// R10: single fused kernel. Phase A: U = X@Win + bias (1-term fp16
//      HMMA, 136 rows incl. 8-row boundary strip) -> U kept in SMEM as
//      fp16. Phase B: 7-step recurrence (R8/R9 rnn), U reads now LDS.
//      No g_U global round-trip, one launch fewer.
// SMEM overlay:  [U 71808)[X 71808)[Win ring 4x8K)     (phase A)
//                [U 71808)[H 67584)...[W ring 8x8K)    (phase B)
// =====================================================================

namespace {
constexpr int Ll = 2048, Dd = 256, Ks = 8, ROWS = 16384;
constexpr int NCH  = 16;               // k-chunks of 16
constexpr int WCH  = 8192;             // packed chunk image: 256n x 32B
constexpr int HSTR = 264;              // row stride in halfs (padded)
constexpr int TM   = 128;              // output rows per CTA
constexpr int NT   = 256;              // 8 warps
constexpr int UROWS = 136;             // U rows incl. 8 boundary rows
constexpr int UIMG  = UROWS * HSTR * 2;            // 71808
constexpr int XOFF  = UIMG;                        // X image (phase A)
constexpr int HOFF  = UIMG;                        // H image (phase B, over X)
constexpr int RINGOFF = XOFF + UIMG;               // 143616
constexpr int WINRING = 4;                         // Win slots (phase A)
constexpr int WRING   = 8;                         // W slots (phase B)
constexpr int SMEM_DYN = RINGOFF + WRING * WCH;    // 209152
constexpr int GTOT = (Ks - 1) * NCH;               // 112 W chunk-uses
}

__device__ __align__(16) __half g_Wf[NCH * 4096];
__device__ __align__(16) __half g_WIf[NCH * 4096];
__device__ float g_itau[Dd];

// ------------------------- PTX helpers --------------------------------
__device__ __forceinline__ uint32_t smem_u32(const void* p) {
    uint32_t a;
    asm("{ .reg .u64 t; cvta.to.shared.u64 t, %1; cvt.u32.u64 %0, t; }"
        : "=r"(a) : "l"(p));
    return a;
}

#define MBARRIER_INIT(mbar, cnt) \
    asm volatile("mbarrier.init.shared.b64 [%0], %1;" \
                 :: "r"((uint32_t)(mbar)), "r"((uint32_t)(cnt)) : "memory")
#define MBARRIER_ARRIVE(mbar) \
    asm volatile("mbarrier.arrive.shared.b64 _, [%0];" \
                 :: "r"((uint32_t)(mbar)) : "memory")
#define MBARRIER_EXPECT_TX(mbar, bytes) \
    asm volatile("mbarrier.arrive.expect_tx.shared.b64 _, [%0], %1;" \
                 :: "r"((uint32_t)(mbar)), "r"((uint32_t)(bytes)) : "memory")
#define MBARRIER_WAIT_PARITY(mbar, parity) do {                               \
    uint32_t _m = (uint32_t)(mbar);                                           \
    uint32_t _p = (uint32_t)(parity);                                         \
    uint32_t _done;                                                           \
    asm volatile(                                                             \
        "{\n\t.reg .pred p;\n\t"                                              \
        "mbarrier.try_wait.parity.acquire.cta.shared::cta.b64 p, [%1], %2;\n\t" \
        "selp.b32 %0, 1, 0, p;\n\t}"                                          \
        : "=r"(_done) : "r"(_m), "r"(_p) : "memory");                         \
    if (!_done) {                                                             \
        asm volatile(                                                         \
            "{\n\t.reg .pred P1;\n\t"                                         \
            "WL_%=:\n\t"                                                      \
            "mbarrier.try_wait.parity.acquire.cta.shared::cta.b64 P1, [%0], %1, 0x989680;\n\t" \
            "@P1 bra.uni WD_%=;\n\t"                                          \
            "bra.uni WL_%=;\n\t"                                              \
            "WD_%=:\n\t}"                                                     \
            :: "r"(_m), "r"(_p) : "memory");                                  \
    }                                                                         \
} while (0)

#define BULK_G2S(dst, src, bytes, mbar)                                       \
    asm volatile(                                                             \
        "cp.async.bulk.shared::cluster.global.mbarrier::complete_tx::bytes "  \
        "[%0], [%1], %2, [%3];"                                               \
        :: "r"((uint32_t)(dst)), "l"(src), "r"((uint32_t)(bytes)),            \
           "r"((uint32_t)(mbar)) : "memory")

#define LDSM_X4(r, addr)                                                      \
    asm volatile("ldmatrix.sync.aligned.m8n8.x4.shared.b16 "                  \
                 "{%0,%1,%2,%3}, [%4];"                                       \
                 : "=r"((r)[0]), "=r"((r)[1]), "=r"((r)[2]), "=r"((r)[3])     \
                 : "r"(addr))

#define MMAH(d, a, b0_, b1_)                                                  \
    asm volatile(                                                             \
        "mma.sync.aligned.m16n8k16.row.col.f32.f16.f16.f32 "                  \
        "{%0,%1,%2,%3},{%4,%5,%6,%7},{%8,%9},{%0,%1,%2,%3};"                  \
        : "+f"((d)[0]), "+f"((d)[1]), "+f"((d)[2]), "+f"((d)[3])              \
        : "r"((a)[0]), "r"((a)[1]), "r"((a)[2]), "r"((a)[3]),                 \
          "r"(b0_), "r"(b1_))

#define MMAHS(d, a, b0_, b1_)                                                 \
    asm volatile(                                                             \
        "mma.sync.aligned.m16n8k16.row.col.f32.f16.f16.f32 "                  \
        "{%0,%1,%2,%3},{%4,%5,%6,%7},{%8,%9},{%0,%1,%2,%3};"                  \
        : "+f"((d)[0]), "+f"((d)[1]), "+f"((d)[2]), "+f"((d)[3])              \
        : "r"((a)[0]), "r"((a)[1]), "r"((a)[2]), "r"((a)[3]),                 \
          "r"(b0_), "r"(b1_))

__device__ __forceinline__ uint32_t pack_hi(float x, float y) {
    __half2 p = __floats2half2_rn(x, y);
    return *(uint32_t*)&p;
}

// ====================== k0: W prep (unchanged, 32 blocks) =============
__global__ __launch_bounds__(256) void w_prep_kernel(const float* __restrict__ W,
                                                     const float* __restrict__ Win,
                                                     const float* __restrict__ tau) {
    __shared__ float tile[16][256];
    const int c   = blockIdx.x >> 1;
    const int m   = blockIdx.x & 1;
    const int tid = threadIdx.x;         // = n
    const float* src = m ? Win : W;
    __half* dst = m ? g_WIf : g_Wf;
    if (blockIdx.x == 0 && tid < Dd) g_itau[tid] = 1.0f / tau[tid];

#pragma unroll
    for (int kk = 0; kk < 16; kk++)
        tile[kk][tid] = src[(size_t)(c * 16 + kk) * Dd + tid];
    __syncthreads();

    const uint32_t nsw = ((uint32_t)(tid >> 2) & 1u);
#pragma unroll
    for (int kh = 0; kh < 2; kh++) {
        uint32_t off = (uint32_t)c * 8192u + (uint32_t)tid * 32u +
                       (((uint32_t)kh ^ nsw) << 4);
        __half h8[8];
#pragma unroll
        for (int j = 0; j < 8; j++)
            h8[j] = __float2half_rn(tile[kh * 8 + j][tid]);
        *(uint4*)((char*)dst + off) = *(uint4*)h8;
    }
}

// ====================== k1: fused U-GEMM + RNN ========================
__global__ __launch_bounds__(NT, 1) void fused_kernel(const float* __restrict__ X,
                                                      const float* __restrict__ bias,
                                                      float* __restrict__ out) {
    extern __shared__ __align__(128) char dsmem[];
    __shared__ __align__(8) uint64_t s_wif[WINRING], s_wie[WINRING];
    __shared__ __align__(8) uint64_t s_wf[WRING],  s_we[WRING];

    const int tid = threadIdx.x;
    const int wid = tid >> 5;
    const int t   = tid & 31;
    const int mi  = wid >> 2;   // 0/1
    const int nj  = wid & 3;    // 0..3

    const uint32_t base = smem_u32(dsmem);
    const uint32_t us   = base;              // U image (fp16)
    const uint32_t xs   = base + XOFF;       // X image (phase A)
    const uint32_t hs   = base + HOFF;       // H image (phase B)
    const uint32_t ring = base + RINGOFF;    // Win ring / W ring
    const uint32_t mwf = smem_u32(s_wif), mwe = smem_u32(s_wie);
    const uint32_t mf  = smem_u32(s_wf),  me  = smem_u32(s_we);
    const int r0 = blockIdx.x * TM;

    if (tid == 0) {
        for (int i = 0; i < WINRING; i++) {
            MBARRIER_INIT(mwf + i * 8, 1);
            MBARRIER_INIT(mwe + i * 8, 8);
        }
        for (int i = 0; i < WRING; i++) {
            MBARRIER_INIT(mf + i * 8, 1);
            MBARRIER_INIT(me + i * 8, 8);
        }
    }
    __syncthreads();

    if (tid == 0) {
#pragma unroll
        for (int s = 0; s < WINRING; s++) {
            MBARRIER_EXPECT_TX(mwf + s * 8, WCH);
            BULK_G2S(ring + s * WCH, (const char*)g_WIf + s * WCH, WCH,
                     mwf + s * 8);
        }
    }

    // ---- load X rows 0..135 (global r0-8+xi), convert to fp16 ----
    for (int xi = wid; xi < UROWS; xi += 8) {
        long gxr = (long)r0 - 8 + xi;
        if (gxr < 0) gxr = 0;                 // values unused when invalid
        const float* xr = X + (size_t)gxr * Dd;
        const int c = t * 8;
        float4 v0 = *(const float4*)(xr + c);
        float4 v1 = *(const float4*)(xr + c + 4);
        uint32_t p[4] = {pack_hi(v0.x, v0.y), pack_hi(v0.z, v0.w),
                         pack_hi(v1.x, v1.y), pack_hi(v1.z, v1.w)};
        *(uint4*)(dsmem + XOFF + (size_t)(xi * HSTR + c) * 2) = *(uint4*)p;
    }
    __syncthreads();

    const int a_r  = ((t >> 3) & 1) * 8 + (t & 7);
    const int a_k  = ((t >> 4) & 1) * 8;
    const int b_n  = ((t >> 4) & 1) * 8 + (t & 7);
    const int kh   = (t >> 3) & 1;
    const int nbase = nj * 64 + b_n;
    const uint32_t sw16 = ((((uint32_t)nbase >> 2) & 1u) ^ (uint32_t)kh) << 4;
    const int nsb = wid * 32 + b_n;           // strip n-slice for this warp
    const uint32_t sws16 = ((((uint32_t)nsb >> 2) & 1u) ^ (uint32_t)kh) << 4;

    // =================== Phase A: U = X @ Win + bias ==================
    {
        float D[4][8][4];
        float Ds[4][4];
#pragma unroll
        for (int i = 0; i < 4; i++)
#pragma unroll
            for (int j = 0; j < 8; j++)
#pragma unroll
                for (int q = 0; q < 4; q++) D[i][j][q] = 0.f;
#pragma unroll
        for (int j = 0; j < 4; j++)
#pragma unroll
            for (int q = 0; q < 4; q++) Ds[j][q] = 0.f;

        for (int g = 0; g < NCH; g++) {
            const int s = g & 3;
            const uint32_t ph = ((uint32_t)g >> 2) & 1u;
            MBARRIER_WAIT_PARITY(mwf + s * 8, ph);

            uint32_t AH[4][4], As[4];
            const int kc = g * 16;
#pragma unroll
            for (int i = 0; i < 4; i++) {
                uint32_t off =
                    (uint32_t)((8 + mi * 64 + i * 16 + a_r) * HSTR + kc + a_k) * 2;
                LDSM_X4(AH[i], xs + off);
            }
            LDSM_X4(As, xs + (uint32_t)(a_r * HSTR + kc + a_k) * 2);

            const uint32_t sb = ring + s * WCH;
            uint32_t BH[4][4], Bs[2][4];
#pragma unroll
            for (int jp = 0; jp < 4; jp++)
                LDSM_X4(BH[jp], sb + (uint32_t)(nbase + jp * 16) * 32 + sw16);
#pragma unroll
            for (int jp = 0; jp < 2; jp++)
                LDSM_X4(Bs[jp], sb + (uint32_t)(nsb + jp * 16) * 32 + sws16);
            __syncwarp();
            if (t == 0) MBARRIER_ARRIVE(mwe + s * 8);

#pragma unroll
            for (int jp = 0; jp < 4; jp++)
#pragma unroll
                for (int i = 0; i < 4; i++) {
                    MMAH(D[i][2 * jp],     AH[i], BH[jp][0], BH[jp][1]);
                    MMAH(D[i][2 * jp + 1], AH[i], BH[jp][2], BH[jp][3]);
                }
#pragma unroll
            for (int jp = 0; jp < 2; jp++) {
                MMAHS(Ds[2 * jp],     As, Bs[jp][0], Bs[jp][1]);
                MMAHS(Ds[2 * jp + 1], As, Bs[jp][2], Bs[jp][3]);
            }

            if (tid == 0 && g + WINRING < NCH) {
                MBARRIER_WAIT_PARITY(mwe + s * 8, ph);
                const int cp = g + WINRING;
                MBARRIER_EXPECT_TX(mwf + s * 8, WCH);
                BULK_G2S(ring + s * WCH, (const char*)g_WIf + cp * WCH, WCH,
                         mwf + s * 8);
            }
        }

        // ---- epilogue A: U = D + bias -> SMEM fp16 ----
#pragma unroll
        for (int i = 0; i < 4; i++) {
#pragma unroll
            for (int half = 0; half < 2; half++) {
                const int ru = 8 + mi * 64 + i * 16 + (t >> 2) + half * 8;
#pragma unroll
                for (int j = 0; j < 8; j++) {
                    const int cc = nj * 64 + j * 8 + 2 * (t & 3);
                    float2 b = *(const float2*)(bias + cc);
                    *(uint32_t*)(dsmem + (size_t)(ru * HSTR + cc) * 2) =
                        pack_hi(D[i][j][half * 2] + b.x,
                                D[i][j][half * 2 + 1] + b.y);
                }
            }
        }
        // strip rows 0..15 (rows 8..15 double-written with identical bits)
#pragma unroll
        for (int half = 0; half < 2; half++) {
            const int ru = (t >> 2) + half * 8;
#pragma unroll
            for (int jn = 0; jn < 4; jn++) {
                const int cc = wid * 32 + jn * 8 + 2 * (t & 3);
                float2 b = *(const float2*)(bias + cc);
                *(uint32_t*)(dsmem + (size_t)(ru * HSTR + cc) * 2) =
                    pack_hi(Ds[jn][half * 2] + b.x,
                            Ds[jn][half * 2 + 1] + b.y);
            }
        }
    }
    __syncthreads();   // U complete; X + Win ring dead

    // Prime W ring (region overlaps dead X tail / Win ring)
    if (tid == 0) {
#pragma unroll
        for (int s = 0; s < WRING; s++) {
            MBARRIER_EXPECT_TX(mf + s * 8, WCH);
            BULK_G2S(ring + s * WCH, (const char*)g_Wf + s * WCH, WCH,
                     mf + s * 8);
        }
    }

    // ---- step 0: h1 = itau * relu(u_{l-7})  (U row rl+1) ----
    for (int rr = wid; rr < TM; rr += 8) {
        const int gr = r0 + rr;
        const int l  = gr & (Ll - 1);
        const int c  = t * 8;
        float u[8];
        if (l >= Ks - 1) {
            uint4 up = *(uint4*)(dsmem + (size_t)((rr + 1) * HSTR + c) * 2);
            uint32_t uw[4] = {up.x, up.y, up.z, up.w};
#pragma unroll
            for (int q = 0; q < 4; q++) {
                __half2 h2 = *(__half2*)&uw[q];
                u[2 * q]     = __half2float(__low2half(h2));
                u[2 * q + 1] = __half2float(__high2half(h2));
            }
        } else {
            float4 b0 = *(const float4*)(bias + c);
            float4 b1 = *(const float4*)(bias + c + 4);
            u[0] = b0.x; u[1] = b0.y; u[2] = b0.z; u[3] = b0.w;
            u[4] = b1.x; u[5] = b1.y; u[6] = b1.z; u[7] = b1.w;
        }
        float4 i0 = *(const float4*)(g_itau + c);
        float4 i1 = *(const float4*)(g_itau + c + 4);
        float it[8] = {i0.x, i0.y, i0.z, i0.w, i1.x, i1.y, i1.z, i1.w};
        uint32_t p[4];
#pragma unroll
        for (int q = 0; q < 4; q++)
            p[q] = pack_hi(it[2 * q] * fmaxf(u[2 * q], 0.f),
                           it[2 * q + 1] * fmaxf(u[2 * q + 1], 0.f));
        *(uint4*)(dsmem + HOFF + (size_t)(rr * HSTR + c) * 2) = *(uint4*)p;
    }
    __syncthreads();

    // =================== Phase B: 7-step recurrence ===================
    int gg = 0;
    for (int step = 1; step < Ks; step++) {
        float D[4][8][4];
#pragma unroll
        for (int i = 0; i < 4; i++)
#pragma unroll
            for (int j = 0; j < 8; j++)
#pragma unroll
                for (int q = 0; q < 4; q++) D[i][j][q] = 0.f;

        for (int c = 0; c < NCH; c++, gg++) {
            const int s = gg & 7;
            const uint32_t ph = ((uint32_t)gg >> 3) & 1u;
            MBARRIER_WAIT_PARITY(mf + s * 8, ph);

            uint32_t AH[4][4];
            const int kc = c * 16;
#pragma unroll
            for (int i = 0; i < 4; i++) {
                uint32_t off =
                    (uint32_t)((mi * 64 + i * 16 + a_r) * HSTR + kc + a_k) * 2;
                LDSM_X4(AH[i], hs + off);
            }
            const uint32_t sb = ring + s * WCH;
            uint32_t BH[4][4];
#pragma unroll
            for (int jp = 0; jp < 4; jp++)
                LDSM_X4(BH[jp], sb + (uint32_t)(nbase + jp * 16) * 32 + sw16);
            __syncwarp();
            if (t == 0) MBARRIER_ARRIVE(me + s * 8);

#pragma unroll
            for (int jp = 0; jp < 4; jp++)
#pragma unroll
                for (int i = 0; i < 4; i++) {
                    MMAH(D[i][2 * jp],     AH[i], BH[jp][0], BH[jp][1]);
                    MMAH(D[i][2 * jp + 1], AH[i], BH[jp][2], BH[jp][3]);
                }

            if (tid == 0 && gg + WRING < GTOT) {
                MBARRIER_WAIT_PARITY(me + s * 8, ph);
                const int cp = (gg + WRING) & 15;
                MBARRIER_EXPECT_TX(mf + s * 8, WCH);
                BULK_G2S(ring + s * WCH, (const char*)g_Wf + cp * WCH, WCH,
                         mf + s * 8);
            }
        }
        __syncthreads();   // all A-reads of H done before epilogue writes

        // ---- fused epilogue: h' = h + itau*(relu(D+u) - h) ----
        const bool last = (step == Ks - 1);
#pragma unroll
        for (int i = 0; i < 4; i++) {
#pragma unroll
            for (int half = 0; half < 2; half++) {
                const int rl = mi * 64 + i * 16 + (t >> 2) + half * 8;
                const int gr = r0 + rl;
                const int tt = (gr & (Ll - 1)) - (Ks - 1) + step;
                const int ur = rl + step + 1;      // U image row
#pragma unroll
                for (int j = 0; j < 8; j++) {
                    const int cc = nj * 64 + j * 8 + 2 * (t & 3);
                    float2 u;
                    if (tt >= 0) {
                        uint32_t uv =
                            *(uint32_t*)(dsmem + (size_t)(ur * HSTR + cc) * 2);
                        __half2 uh = *(__half2*)&uv;
                        u = make_float2(__half2float(__low2half(uh)),
                                        __half2float(__high2half(uh)));
                    } else {
                        u = *(const float2*)(bias + cc);
                    }
                    float2 it = *(const float2*)(g_itau + cc);
                    const float d0 = D[i][j][half * 2];
                    const float d1 = D[i][j][half * 2 + 1];
                    char* hb = dsmem + HOFF + (size_t)(rl * HSTR + cc) * 2;
                    uint32_t hv = *(uint32_t*)(hb);
                    __half2 hh = *(__half2*)&hv;
                    float h0 = __half2float(__low2half(hh));
                    float h1 = __half2float(__high2half(hh));
                    float s0 = fmaxf(d0 + u.x, 0.f);
                    float s1 = fmaxf(d1 + u.y, 0.f);
                    float n0 = h0 + it.x * (s0 - h0);
                    float n1 = h1 + it.y * (s1 - h1);
                    if (last) {
                        *(float2*)(out + (size_t)gr * Dd + cc) =
                            make_float2(n0, n1);
                    } else {
                        *(uint32_t*)(hb) = pack_hi(n0, n1);
                    }
                }
            }
        }
        if (!last) __syncthreads();
    }
}

// ---------------------------------------------------------------------------
extern "C" void kernel_launch(void* const* d_in, const int* in_sizes, int n_in,
                              void* d_out, int out_size) {
    (void)in_sizes; (void)n_in; (void)out_size;
    const float* x            = (const float*)d_in[0];
    const float* weight       = (const float*)d_in[1];
    const float* input_weight = (const float*)d_in[2];
    const float* bias         = (const float*)d_in[3];
    const float* tau          = (const float*)d_in[4];
    float* out = (float*)d_out;

    w_prep_kernel<<<2 * NCH, 256>>>(weight, input_weight, tau);

    cudaFuncSetAttribute(fused_kernel, cudaFuncAttributeMaxDynamicSharedMemorySize,
                         SMEM_DYN);
    fused_kernel<<<ROWS / TM, NT, SMEM_DYN>>>(x, bias, out);
}